// round 1
// baseline (speedup 1.0000x reference)
#include <cuda_runtime.h>
#include <math.h>

#define B_  4
#define S_  1024
#define H_  768
#define NH_ 12
#define DH_ 64
#define NEGV -100000.0f

// Scratch (allocation-free rule: __device__ globals)
__device__ float g_hs [B_*S_*H_];
__device__ float g_ctx[B_*S_*H_];
__device__ float g_q  [B_*S_*H_];   // layout (b, h, s, d)
__device__ float g_k  [B_*S_*H_];
__device__ float g_v  [B_*S_*H_];

// ---------------------------------------------------------------------------
// 1) hs = hidden + (s < feat_len[b] ? vis : 0); ctx = context + same
// ---------------------------------------------------------------------------
__global__ void addpos_kernel(const float4* __restrict__ hidden,
                              const float4* __restrict__ context,
                              const float4* __restrict__ vis,
                              const int*    __restrict__ feat_len) {
    int idx = blockIdx.x * blockDim.x + threadIdx.x;
    const int n4 = B_*S_*H_/4;
    if (idx >= n4) return;
    int e = idx * 4;
    int b = e / (S_*H_);
    int s = (e / H_) % S_;
    float4 h = hidden[idx];
    float4 c = context[idx];
    if (s < feat_len[b]) {
        float4 a = vis[idx];
        h.x += a.x; h.y += a.y; h.z += a.z; h.w += a.w;
        c.x += a.x; c.y += a.y; c.z += a.z; c.w += a.w;
    }
    reinterpret_cast<float4*>(g_hs )[idx] = h;
    reinterpret_cast<float4*>(g_ctx)[idx] = c;
}

// ---------------------------------------------------------------------------
// 2) Q/K/V projection: C[m,n] = sum_k A[m,k] * W[n,k] + bias[n]
//    M = B*S = 4096, N = K = 768. Output stored head-major (b,h,s,d).
//    which: 0 -> Q from hs, 1 -> K from ctx, 2 -> V from ctx
// ---------------------------------------------------------------------------
#define BM 128
#define BN 64
#define BK 16

__global__ __launch_bounds__(256) void qkv_gemm_kernel(int which,
        const float* __restrict__ W, const float* __restrict__ bias) {
    const float* A = (which == 0) ? g_hs : g_ctx;
    float* C = (which == 0) ? g_q : (which == 1) ? g_k : g_v;

    __shared__ float As[BK][BM + 4];
    __shared__ float Bs[BK][BN];

    int tid = threadIdx.x;
    int bm0 = blockIdx.x * BM;
    int bn0 = blockIdx.y * BN;
    int tx = tid & 15;       // 16 col-groups of 4
    int ty = tid >> 4;       // 16 row-groups of 8

    float acc[8][4];
    #pragma unroll
    for (int i = 0; i < 8; i++)
        #pragma unroll
        for (int j = 0; j < 4; j++) acc[i][j] = 0.f;

    for (int k0 = 0; k0 < H_; k0 += BK) {
        // Load A tile (128x16) transposed into As[k][m]
        #pragma unroll
        for (int it = 0; it < 2; it++) {
            int i = tid + it * 256;
            int m = i >> 2, kq = i & 3;
            float4 va = *reinterpret_cast<const float4*>(
                A + (size_t)(bm0 + m) * H_ + k0 + kq * 4);
            As[kq*4+0][m] = va.x; As[kq*4+1][m] = va.y;
            As[kq*4+2][m] = va.z; As[kq*4+3][m] = va.w;
        }
        // Load W tile (64x16) transposed into Bs[k][n]
        {
            int n = tid >> 2, kq = tid & 3;
            float4 vb = *reinterpret_cast<const float4*>(
                W + (size_t)(bn0 + n) * H_ + k0 + kq * 4);
            Bs[kq*4+0][n] = vb.x; Bs[kq*4+1][n] = vb.y;
            Bs[kq*4+2][n] = vb.z; Bs[kq*4+3][n] = vb.w;
        }
        __syncthreads();

        #pragma unroll
        for (int kk = 0; kk < BK; kk++) {
            float4 a0 = *reinterpret_cast<float4*>(&As[kk][ty*8]);
            float4 a1 = *reinterpret_cast<float4*>(&As[kk][ty*8+4]);
            float4 b0 = *reinterpret_cast<float4*>(&Bs[kk][tx*4]);
            float av[8] = {a0.x,a0.y,a0.z,a0.w,a1.x,a1.y,a1.z,a1.w};
            float bv[4] = {b0.x,b0.y,b0.z,b0.w};
            #pragma unroll
            for (int i = 0; i < 8; i++)
                #pragma unroll
                for (int j = 0; j < 4; j++)
                    acc[i][j] += av[i] * bv[j];
        }
        __syncthreads();
    }

    // Epilogue: BN==DH so this block covers exactly one head slice
    int h = bn0 / DH_;
    float4 bv = *reinterpret_cast<const float4*>(bias + bn0 + tx*4);
    #pragma unroll
    for (int i = 0; i < 8; i++) {
        int m = bm0 + ty*8 + i;
        int b = m >> 10;          // S_ = 1024
        int s = m & 1023;
        float4 o;
        o.x = acc[i][0] + bv.x; o.y = acc[i][1] + bv.y;
        o.z = acc[i][2] + bv.z; o.w = acc[i][3] + bv.w;
        *reinterpret_cast<float4*>(
            C + (((size_t)(b*NH_ + h) * S_ + s) * DH_ + tx*4)) = o;
    }
}

// ---------------------------------------------------------------------------
// 3) scores[b,h,q,k]: NEG for masked entries, else (q.k)/8 * gate + amask
//    One CTA per (bh, q) row; 256 threads x 4 floats = 1024 cols.
// ---------------------------------------------------------------------------
__global__ __launch_bounds__(256) void scores_kernel(
        const float* __restrict__ gate, const float* __restrict__ amask,
        const int* __restrict__ feat_len, const int* __restrict__ ppos,
        float* __restrict__ scores) {
    int q  = blockIdx.x;
    int bh = blockIdx.y;
    int b  = bh / NH_;
    int P  = ppos ? ppos[0] : 512;
    int fl = feat_len[b];

    __shared__ float qrow[DH_];
    if (threadIdx.x < DH_)
        qrow[threadIdx.x] = g_q[((size_t)bh * S_ + q) * DH_ + threadIdx.x];
    __syncthreads();

    int k0 = threadIdx.x * 4;
    float res[4];
    #pragma unroll
    for (int j = 0; j < 4; j++) {
        int k = k0 + j;
        bool masked;
        if      (q <  P-1) masked = (k > q) || (k < q-1);
        else if (q == P-1) masked = false;
        else               masked = (k >= P) || (k < fl-1);
        if (masked) {
            res[j] = NEGV;
        } else {
            const float4* kp = reinterpret_cast<const float4*>(
                g_k + ((size_t)bh * S_ + k) * DH_);
            float dot = 0.f;
            #pragma unroll
            for (int d4 = 0; d4 < DH_/4; d4++) {
                float4 kv = __ldg(&kp[d4]);
                dot += qrow[d4*4+0]*kv.x + qrow[d4*4+1]*kv.y
                     + qrow[d4*4+2]*kv.z + qrow[d4*4+3]*kv.w;
            }
            res[j] = dot * 0.125f * gate[((size_t)b * S_ + q) * S_ + k]
                   + amask[b * S_ + k];
        }
    }
    float4 o = make_float4(res[0], res[1], res[2], res[3]);
    *reinterpret_cast<float4*>(scores + ((size_t)bh * S_ + q) * S_ + k0) = o;
}

// ---------------------------------------------------------------------------
// 4a) Rows q < P-1: only k in {q-1, q} survive. out = softmax2 . v
//     256 threads = 4 rows x 64 d.
// ---------------------------------------------------------------------------
__global__ void softmax_sparse_kernel(const float* __restrict__ scores,
                                      const int* __restrict__ ppos,
                                      float* __restrict__ out) {
    int tid = threadIdx.x;
    int R = blockIdx.x * 4 + (tid >> 6);   // row over B*NH*S
    int d = tid & 63;
    int bh = R >> 10;
    int q  = R & 1023;
    int P  = ppos ? ppos[0] : 512;
    if (q >= P-1) return;
    int b = bh / NH_, h = bh % NH_;
    const float* srow = scores + (size_t)R * S_;

    float val;
    if (q == 0) {
        val = g_v[((size_t)bh * S_) * DH_ + d];   // single surviving entry
    } else {
        float s0 = srow[q-1], s1 = srow[q];
        float m = fmaxf(s0, s1);
        float p0 = expf(s0 - m), p1 = expf(s1 - m);
        float inv = 1.f / (p0 + p1);               // masked entries underflow to 0
        val = (p0 * g_v[((size_t)bh*S_ + q-1)*DH_ + d]
             + p1 * g_v[((size_t)bh*S_ + q  )*DH_ + d]) * inv;
    }
    out[((size_t)(b*S_ + q)) * H_ + h*DH_ + d] = val;
}

// ---------------------------------------------------------------------------
// 4b) Rows q >= P-1: dense softmax over the surviving span + PV.
//     q == P-1: full row. q >= P: k in [max(0,fl-1), P). Empty span -> uniform.
// ---------------------------------------------------------------------------
__global__ __launch_bounds__(128) void softmax_dense_kernel(
        const float* __restrict__ scores, const int* __restrict__ feat_len,
        const int* __restrict__ ppos, float* __restrict__ out) {
    int q  = blockIdx.x;
    int bh = blockIdx.y;
    int P  = ppos ? ppos[0] : 512;
    if (q < P-1) return;
    int b = bh / NH_, h = bh % NH_;
    int fl = feat_len[b];

    int lo, hi; bool uniform = false;
    if (q == P-1) { lo = 0; hi = S_; }
    else {
        lo = max(0, fl-1); hi = P;
        if (lo >= hi) { lo = 0; hi = S_; uniform = true; }  // all masked -> 1/S each
    }

    __shared__ float p[S_];
    __shared__ float red[128];
    const float* srow = scores + ((size_t)bh * S_ + q) * S_;
    int tid = threadIdx.x;

    float M = -INFINITY;
    if (!uniform) {
        for (int k = lo + tid; k < hi; k += 128) M = fmaxf(M, srow[k]);
        red[tid] = M; __syncthreads();
        for (int off = 64; off > 0; off >>= 1) {
            if (tid < off) red[tid] = fmaxf(red[tid], red[tid + off]);
            __syncthreads();
        }
        M = red[0];
        __syncthreads();
    }

    float lsum = 0.f;
    for (int k = lo + tid; k < hi; k += 128) {
        float e = uniform ? 1.0f : expf(srow[k] - M);
        p[k - lo] = e;
        lsum += e;
    }
    red[tid] = lsum; __syncthreads();
    for (int off = 64; off > 0; off >>= 1) {
        if (tid < off) red[tid] += red[tid + off];
        __syncthreads();
    }
    float inv = 1.f / red[0];
    __syncthreads();

    // PV: 128 threads = 2 k-halves x 64 d
    int d = tid & 63, half = tid >> 6;
    int span = hi - lo;
    int mid = lo + (span >> 1);
    int kb = half ? mid : lo;
    int ke = half ? hi  : mid;
    float acc = 0.f;
    for (int k = kb; k < ke; k++)
        acc += p[k - lo] * g_v[((size_t)bh * S_ + k) * DH_ + d];
    red[tid] = acc; __syncthreads();
    if (tid < 64)
        out[((size_t)(b*S_ + q)) * H_ + h*DH_ + tid] = (red[tid] + red[tid+64]) * inv;
}

// ---------------------------------------------------------------------------
extern "C" void kernel_launch(void* const* d_in, const int* in_sizes, int n_in,
                              void* d_out, int out_size) {
    const float* hidden  = (const float*)d_in[0];
    const float* context = (const float*)d_in[1];
    const float* amask   = (const float*)d_in[2];
    const float* gate    = (const float*)d_in[3];
    const float* vis     = (const float*)d_in[4];
    const float* Wq      = (const float*)d_in[5];
    const float* bq      = (const float*)d_in[6];
    const float* Wk      = (const float*)d_in[7];
    const float* bk      = (const float*)d_in[8];
    const float* Wv      = (const float*)d_in[9];
    const float* bv      = (const float*)d_in[10];
    const int*   feat_len= (const int*)  d_in[11];
    const int*   ppos    = (n_in > 12) ? (const int*)d_in[12] : nullptr;

    float* out    = (float*)d_out;                       // (B,S,H)
    float* scores = out + (size_t)B_ * S_ * H_;          // (B,NH,S,S)

    addpos_kernel<<<(B_*S_*H_/4 + 255)/256, 256>>>(
        (const float4*)hidden, (const float4*)context,
        (const float4*)vis, feat_len);

    dim3 gg((B_*S_)/BM, H_/BN);
    qkv_gemm_kernel<<<gg, 256>>>(0, Wq, bq);
    qkv_gemm_kernel<<<gg, 256>>>(1, Wk, bk);
    qkv_gemm_kernel<<<gg, 256>>>(2, Wv, bv);

    scores_kernel<<<dim3(S_, B_*NH_), 256>>>(gate, amask, feat_len, ppos, scores);

    softmax_sparse_kernel<<<(B_*NH_*S_)/4, 256>>>(scores, ppos, out);
    softmax_dense_kernel<<<dim3(S_, B_*NH_), 128>>>(scores, feat_len, ppos, out);
}

// round 2
// speedup vs baseline: 1.3796x; 1.3796x over previous
#include <cuda_runtime.h>
#include <math.h>

#define B_  4
#define S_  1024
#define H_  768
#define NH_ 12
#define DH_ 64
#define NEGV -100000.0f

// Scratch (allocation-free rule: __device__ globals)
__device__ float g_hs [B_*S_*H_];
__device__ float g_ctx[B_*S_*H_];
__device__ float g_q  [B_*S_*H_];   // layout (b, h, s, d)
__device__ float g_k  [B_*S_*H_];
__device__ float g_v  [B_*S_*H_];

// ---------------------------------------------------------------------------
// 1) hs = hidden + (s < feat_len[b] ? vis : 0); ctx = context + same
// ---------------------------------------------------------------------------
__global__ void addpos_kernel(const float4* __restrict__ hidden,
                              const float4* __restrict__ context,
                              const float4* __restrict__ vis,
                              const int*    __restrict__ feat_len) {
    int idx = blockIdx.x * blockDim.x + threadIdx.x;
    const int n4 = B_*S_*H_/4;
    if (idx >= n4) return;
    int e = idx * 4;
    int b = e / (S_*H_);
    int s = (e / H_) % S_;
    float4 h = hidden[idx];
    float4 c = context[idx];
    if (s < feat_len[b]) {
        float4 a = vis[idx];
        h.x += a.x; h.y += a.y; h.z += a.z; h.w += a.w;
        c.x += a.x; c.y += a.y; c.z += a.z; c.w += a.w;
    }
    reinterpret_cast<float4*>(g_hs )[idx] = h;
    reinterpret_cast<float4*>(g_ctx)[idx] = c;
}

// ---------------------------------------------------------------------------
// 2) QKV projection, fused (grid.z selects Q/K/V).
//    C[m,n] = sum_k A[m,k] * W[n,k] + bias[n], output in (b,h,s,d).
//    128x128x8 tiles, 256 threads, 8x8 per thread (4+4 split), double-buffered.
// ---------------------------------------------------------------------------
__global__ __launch_bounds__(256, 2) void qkv_gemm2(
        const float* __restrict__ Wq, const float* __restrict__ bq,
        const float* __restrict__ Wk, const float* __restrict__ bk,
        const float* __restrict__ Wv, const float* __restrict__ bv) {
    int which = blockIdx.z;
    const float* A    = (which == 0) ? g_hs : g_ctx;
    const float* W    = (which == 0) ? Wq : (which == 1) ? Wk : Wv;
    const float* bias = (which == 0) ? bq : (which == 1) ? bk : bv;
    float* C          = (which == 0) ? g_q : (which == 1) ? g_k : g_v;

    __shared__ float As[2][8][132];
    __shared__ float Bs[2][8][132];

    int tid = threadIdx.x;
    int bm0 = blockIdx.x * 128;
    int bn0 = blockIdx.y * 128;
    int lm = tid >> 1;            // 0..127
    int lk = (tid & 1) * 4;       // 0 or 4
    const float* Aptr = A + (size_t)(bm0 + lm) * H_ + lk;
    const float* Wptr = W + (size_t)(bn0 + lm) * H_ + lk;

    // prologue: tile 0 -> buffer 0
    float4 ra = *reinterpret_cast<const float4*>(Aptr);
    float4 rb = *reinterpret_cast<const float4*>(Wptr);
    As[0][lk+0][lm] = ra.x; As[0][lk+1][lm] = ra.y;
    As[0][lk+2][lm] = ra.z; As[0][lk+3][lm] = ra.w;
    Bs[0][lk+0][lm] = rb.x; Bs[0][lk+1][lm] = rb.y;
    Bs[0][lk+2][lm] = rb.z; Bs[0][lk+3][lm] = rb.w;
    __syncthreads();

    int ty = tid >> 4;   // 0..15 -> rows ty*4 and 64+ty*4
    int tx = tid & 15;   // 0..15 -> cols tx*4 and 64+tx*4

    float acc[8][8];
    #pragma unroll
    for (int i = 0; i < 8; i++)
        #pragma unroll
        for (int j = 0; j < 8; j++) acc[i][j] = 0.f;

    const int NT = H_ / 8;   // 96
    for (int t = 0; t < NT; t++) {
        int cur = t & 1;
        if (t + 1 < NT) {
            ra = *reinterpret_cast<const float4*>(Aptr + (t+1)*8);
            rb = *reinterpret_cast<const float4*>(Wptr + (t+1)*8);
        }
        #pragma unroll
        for (int kk = 0; kk < 8; kk++) {
            float4 a0 = *reinterpret_cast<float4*>(&As[cur][kk][ty*4]);
            float4 a1 = *reinterpret_cast<float4*>(&As[cur][kk][64 + ty*4]);
            float4 b0 = *reinterpret_cast<float4*>(&Bs[cur][kk][tx*4]);
            float4 b1 = *reinterpret_cast<float4*>(&Bs[cur][kk][64 + tx*4]);
            float av[8] = {a0.x,a0.y,a0.z,a0.w, a1.x,a1.y,a1.z,a1.w};
            float bw[8] = {b0.x,b0.y,b0.z,b0.w, b1.x,b1.y,b1.z,b1.w};
            #pragma unroll
            for (int i = 0; i < 8; i++)
                #pragma unroll
                for (int j = 0; j < 8; j++)
                    acc[i][j] += av[i] * bw[j];
        }
        if (t + 1 < NT) {
            int nb = (t + 1) & 1;
            As[nb][lk+0][lm] = ra.x; As[nb][lk+1][lm] = ra.y;
            As[nb][lk+2][lm] = ra.z; As[nb][lk+3][lm] = ra.w;
            Bs[nb][lk+0][lm] = rb.x; Bs[nb][lk+1][lm] = rb.y;
            Bs[nb][lk+2][lm] = rb.z; Bs[nb][lk+3][lm] = rb.w;
        }
        __syncthreads();
    }

    // Epilogue: two column halves (each stays within one head since 4 | 64)
    #pragma unroll
    for (int ch = 0; ch < 2; ch++) {
        int n0 = bn0 + ch*64 + tx*4;
        int h = n0 >> 6, d0 = n0 & 63;
        float4 bb = *reinterpret_cast<const float4*>(bias + n0);
        #pragma unroll
        for (int i = 0; i < 8; i++) {
            int m = bm0 + (i < 4 ? ty*4 + i : 64 + ty*4 + (i-4));
            int b = m >> 10;
            int s = m & 1023;
            float4 o;
            o.x = acc[i][ch*4+0] + bb.x; o.y = acc[i][ch*4+1] + bb.y;
            o.z = acc[i][ch*4+2] + bb.z; o.w = acc[i][ch*4+3] + bb.w;
            *reinterpret_cast<float4*>(
                C + (((size_t)(b*NH_ + h) * S_ + s) * DH_ + d0)) = o;
        }
    }
}

// ---------------------------------------------------------------------------
// 3) scores[b,h,q,k]: NEG for masked entries, else (q.k)/8 * gate + amask
// ---------------------------------------------------------------------------
__global__ __launch_bounds__(256) void scores_kernel(
        const float* __restrict__ gate, const float* __restrict__ amask,
        const int* __restrict__ feat_len, const int* __restrict__ ppos,
        float* __restrict__ scores) {
    int q  = blockIdx.x;
    int bh = blockIdx.y;
    int b  = bh / NH_;
    int P  = ppos ? ppos[0] : 512;
    int fl = feat_len[b];

    __shared__ float qrow[DH_];
    if (threadIdx.x < DH_)
        qrow[threadIdx.x] = g_q[((size_t)bh * S_ + q) * DH_ + threadIdx.x];
    __syncthreads();

    int k0 = threadIdx.x * 4;
    float res[4];
    #pragma unroll
    for (int j = 0; j < 4; j++) {
        int k = k0 + j;
        bool masked;
        if      (q <  P-1) masked = (k > q) || (k < q-1);
        else if (q == P-1) masked = false;
        else               masked = (k >= P) || (k < fl-1);
        if (masked) {
            res[j] = NEGV;
        } else {
            const float4* kp = reinterpret_cast<const float4*>(
                g_k + ((size_t)bh * S_ + k) * DH_);
            float dot = 0.f;
            #pragma unroll
            for (int d4 = 0; d4 < DH_/4; d4++) {
                float4 kv = __ldg(&kp[d4]);
                dot += qrow[d4*4+0]*kv.x + qrow[d4*4+1]*kv.y
                     + qrow[d4*4+2]*kv.z + qrow[d4*4+3]*kv.w;
            }
            res[j] = dot * 0.125f * gate[((size_t)b * S_ + q) * S_ + k]
                   + amask[b * S_ + k];
        }
    }
    float4 o = make_float4(res[0], res[1], res[2], res[3]);
    *reinterpret_cast<float4*>(scores + ((size_t)bh * S_ + q) * S_ + k0) = o;
}

// ---------------------------------------------------------------------------
// 4a) Rows q < P-1: only k in {q-1, q} survive. out = softmax2 . v
// ---------------------------------------------------------------------------
__global__ void softmax_sparse_kernel(const float* __restrict__ scores,
                                      const int* __restrict__ ppos,
                                      float* __restrict__ out) {
    int tid = threadIdx.x;
    int R = blockIdx.x * 4 + (tid >> 6);
    int d = tid & 63;
    int bh = R >> 10;
    int q  = R & 1023;
    int P  = ppos ? ppos[0] : 512;
    if (q >= P-1) return;
    int b = bh / NH_, h = bh % NH_;
    const float* srow = scores + (size_t)R * S_;

    float val;
    if (q == 0) {
        val = g_v[((size_t)bh * S_) * DH_ + d];
    } else {
        float s0 = srow[q-1], s1 = srow[q];
        float m = fmaxf(s0, s1);
        float p0 = expf(s0 - m), p1 = expf(s1 - m);
        float inv = 1.f / (p0 + p1);
        val = (p0 * g_v[((size_t)bh*S_ + q-1)*DH_ + d]
             + p1 * g_v[((size_t)bh*S_ + q  )*DH_ + d]) * inv;
    }
    out[((size_t)(b*S_ + q)) * H_ + h*DH_ + d] = val;
}

// ---------------------------------------------------------------------------
// 4b) Single row q == P-1: full dense softmax + serial PV (only 48 CTAs).
// ---------------------------------------------------------------------------
__global__ __launch_bounds__(128) void row_pm1_kernel(
        const float* __restrict__ scores, const int* __restrict__ ppos,
        float* __restrict__ out) {
    int bh = blockIdx.x;
    int P  = ppos ? ppos[0] : 512;
    int q  = P - 1;
    if (q < 0) return;
    int b = bh / NH_, h = bh % NH_;

    __shared__ float p[S_];
    __shared__ float red[128];
    const float* srow = scores + ((size_t)bh * S_ + q) * S_;
    int tid = threadIdx.x;

    float M = -INFINITY;
    for (int k = tid; k < S_; k += 128) M = fmaxf(M, srow[k]);
    red[tid] = M; __syncthreads();
    for (int off = 64; off > 0; off >>= 1) {
        if (tid < off) red[tid] = fmaxf(red[tid], red[tid + off]);
        __syncthreads();
    }
    M = red[0];
    __syncthreads();

    float lsum = 0.f;
    for (int k = tid; k < S_; k += 128) {
        float e = expf(srow[k] - M);
        p[k] = e; lsum += e;
    }
    red[tid] = lsum; __syncthreads();
    for (int off = 64; off > 0; off >>= 1) {
        if (tid < off) red[tid] += red[tid + off];
        __syncthreads();
    }
    float inv = 1.f / red[0];
    __syncthreads();

    int d = tid & 63, half = tid >> 6;
    int kb = half ? S_/2 : 0;
    int ke = half ? S_   : S_/2;
    float acc = 0.f;
    for (int k = kb; k < ke; k++)
        acc += p[k] * g_v[((size_t)bh * S_ + k) * DH_ + d];
    red[tid] = acc; __syncthreads();
    if (tid < 64)
        out[((size_t)(b*S_ + q)) * H_ + h*DH_ + tid] = (red[tid] + red[tid+64]) * inv;
}

// ---------------------------------------------------------------------------
// 4c) Rows q >= P: tiled softmax+PV. One CTA per (bh, 32-row tile).
//     Span is [max(0,fl-1), P); if empty, the whole row is NEG so using
//     [0,S) gives exp(NEG-NEG)=1 -> uniform 1/S automatically.
// ---------------------------------------------------------------------------
#define QT 32
#define KT 64
__global__ __launch_bounds__(256) void pv_tiled_kernel(
        const float* __restrict__ scores, const int* __restrict__ feat_len,
        const int* __restrict__ ppos, float* __restrict__ out) {
    int bh = blockIdx.y;
    int b = bh / NH_, h = bh % NH_;
    int P = ppos ? ppos[0] : 512;
    int q0 = blockIdx.x * QT;
    if (q0 + QT <= P) return;                // no rows >= P in this tile
    int fl = feat_len[b];
    int lo = max(0, fl - 1), hi = P;
    if (lo >= hi) { lo = 0; hi = S_; }       // fully-masked rows -> uniform

    __shared__ float Vs[KT][DH_ + 4];
    __shared__ float Ps[QT][KT];
    __shared__ float Ms[QT], Is[QT];

    int tid = threadIdx.x;
    int w = tid >> 5, lane = tid & 31;

    // Pass 1: per-row max & inverse-sum (warp w owns rows w*4..w*4+3)
    for (int rr = 0; rr < 4; rr++) {
        int r = w*4 + rr;
        int q = q0 + r;
        if (q < P) continue;
        const float* srow = scores + ((size_t)bh * S_ + q) * S_;
        float m = -INFINITY;
        for (int k = lo + lane; k < hi; k += 32) m = fmaxf(m, srow[k]);
        #pragma unroll
        for (int off = 16; off > 0; off >>= 1)
            m = fmaxf(m, __shfl_xor_sync(0xffffffffu, m, off));
        float s = 0.f;
        for (int k = lo + lane; k < hi; k += 32) s += expf(srow[k] - m);
        #pragma unroll
        for (int off = 16; off > 0; off >>= 1)
            s += __shfl_xor_sync(0xffffffffu, s, off);
        if (lane == 0) { Ms[r] = m; Is[r] = 1.f / s; }
    }
    __syncthreads();

    int d = tid & 63;       // output dim
    int g = tid >> 6;       // row group: rows g*8..g*8+7 (uniform per warp)
    float acc[8];
    #pragma unroll
    for (int j = 0; j < 8; j++) acc[j] = 0.f;

    int pq  = q0 + (tid >> 3);      // row this thread fills probs for
    int pk0 = (tid & 7) * 8;        // 8 consecutive k within the tile
    bool pact = (pq >= P);
    float pM = 0.f, pI = 0.f;
    if (pact) { pM = Ms[tid >> 3]; pI = Is[tid >> 3]; }
    const float* psrow = scores + ((size_t)bh * S_ + pq) * S_;

    for (int kt = lo; kt < hi; kt += KT) {
        __syncthreads();   // previous accumulation done before overwriting smem
        // V tile: 64 x 64, each thread 4 x float4
        #pragma unroll
        for (int it = 0; it < 4; it++) {
            int idx = tid + it * 256;
            int r = idx >> 4, c4 = (idx & 15) * 4;
            float4 v4 = make_float4(0.f, 0.f, 0.f, 0.f);
            if (kt + r < hi)
                v4 = *reinterpret_cast<const float4*>(
                    g_v + ((size_t)bh * S_ + kt + r) * DH_ + c4);
            *reinterpret_cast<float4*>(&Vs[r][c4]) = v4;
        }
        // P tile: 32 x 64
        #pragma unroll
        for (int j = 0; j < 8; j++) {
            int k = kt + pk0 + j;
            float p = 0.f;
            if (pact && k < hi) p = expf(psrow[k] - pM) * pI;
            Ps[tid >> 3][pk0 + j] = p;
        }
        __syncthreads();
        // accumulate: thread (g, d) handles rows g*8..g*8+7
        #pragma unroll 8
        for (int kk = 0; kk < KT; kk++) {
            float vv = Vs[kk][d];
            #pragma unroll
            for (int j = 0; j < 8; j++)
                acc[j] += Ps[g*8 + j][kk] * vv;
        }
    }

    #pragma unroll
    for (int j = 0; j < 8; j++) {
        int q = q0 + g*8 + j;
        if (q >= P)
            out[((size_t)(b*S_ + q)) * H_ + h*DH_ + d] = acc[j];
    }
}

// ---------------------------------------------------------------------------
extern "C" void kernel_launch(void* const* d_in, const int* in_sizes, int n_in,
                              void* d_out, int out_size) {
    const float* hidden  = (const float*)d_in[0];
    const float* context = (const float*)d_in[1];
    const float* amask   = (const float*)d_in[2];
    const float* gate    = (const float*)d_in[3];
    const float* vis     = (const float*)d_in[4];
    const float* Wq      = (const float*)d_in[5];
    const float* bq      = (const float*)d_in[6];
    const float* Wk      = (const float*)d_in[7];
    const float* bk      = (const float*)d_in[8];
    const float* Wv      = (const float*)d_in[9];
    const float* bv      = (const float*)d_in[10];
    const int*   feat_len= (const int*)  d_in[11];
    const int*   ppos    = (n_in > 12) ? (const int*)d_in[12] : nullptr;

    float* out    = (float*)d_out;                       // (B,S,H)
    float* scores = out + (size_t)B_ * S_ * H_;          // (B,NH,S,S)

    addpos_kernel<<<(B_*S_*H_/4 + 255)/256, 256>>>(
        (const float4*)hidden, (const float4*)context,
        (const float4*)vis, feat_len);

    dim3 gg((B_*S_)/128, H_/128, 3);
    qkv_gemm2<<<gg, 256>>>(Wq, bq, Wk, bk, Wv, bv);

    scores_kernel<<<dim3(S_, B_*NH_), 256>>>(gate, amask, feat_len, ppos, scores);

    softmax_sparse_kernel<<<(B_*NH_*S_)/4, 256>>>(scores, ppos, out);
    row_pm1_kernel<<<B_*NH_, 128>>>(scores, ppos, out);
    pv_tiled_kernel<<<dim3(S_/QT, B_*NH_), 256>>>(scores, feat_len, ppos, out);
}

// round 5
// speedup vs baseline: 1.6382x; 1.1874x over previous
#include <cuda_runtime.h>
#include <cuda_bf16.h>
#include <math.h>

#define B_  4
#define S_  1024
#define H_  768
#define NH_ 12
#define DH_ 64
#define NEGV -100000.0f
#define KS  2304              // 3-term split: per k -> [ah, al, ah] x [wh, wh, wl]

// Scratch (allocation-free rule: __device__ globals)
__device__ __nv_bfloat16 g_ahl[2][(size_t)B_*S_*KS]; // 0: hs split, 1: ctx split
__device__ __nv_bfloat16 g_whl[3][(size_t)H_*KS];    // Wq/Wk/Wv split
__device__ float g_q[B_*S_*H_];   // (b,h,s,d)
__device__ float g_k[B_*S_*H_];
__device__ float g_v[B_*S_*H_];

// ---------------------------------------------------------------------------
// 1) Fused: hs/ctx = input + masked vis, then fp32 -> 3-term bf16 split.
//    A-side pattern per element: [hi, lo, hi]
// ---------------------------------------------------------------------------
__global__ void split_a_kernel(const float4* __restrict__ hidden,
                               const float4* __restrict__ context,
                               const float4* __restrict__ vis,
                               const int*    __restrict__ feat_len) {
    int idx = blockIdx.x * blockDim.x + threadIdx.x;   // group of 8 elements
    const int ng = B_*S_*H_/8;
    if (idx >= ng) return;
    int e = idx * 8;
    int m = e / H_;          // 0..4095
    int k = e % H_;
    int b = m >> 10;
    int s = m & 1023;

    float4 h0 = hidden[idx*2], h1 = hidden[idx*2+1];
    float4 c0 = context[idx*2], c1 = context[idx*2+1];
    float hv[8] = {h0.x,h0.y,h0.z,h0.w, h1.x,h1.y,h1.z,h1.w};
    float cv[8] = {c0.x,c0.y,c0.z,c0.w, c1.x,c1.y,c1.z,c1.w};
    if (s < feat_len[b]) {
        float4 a0 = vis[idx*2], a1 = vis[idx*2+1];
        float av[8] = {a0.x,a0.y,a0.z,a0.w, a1.x,a1.y,a1.z,a1.w};
        #pragma unroll
        for (int i = 0; i < 8; i++) { hv[i] += av[i]; cv[i] += av[i]; }
    }

    __align__(16) __nv_bfloat16 bh[24], bc[24];
    #pragma unroll
    for (int i = 0; i < 8; i++) {
        __nv_bfloat16 hi = __float2bfloat16(hv[i]);
        __nv_bfloat16 lo = __float2bfloat16(hv[i] - __bfloat162float(hi));
        bh[3*i] = hi; bh[3*i+1] = lo; bh[3*i+2] = hi;
        __nv_bfloat16 ci = __float2bfloat16(cv[i]);
        __nv_bfloat16 cl = __float2bfloat16(cv[i] - __bfloat162float(ci));
        bc[3*i] = ci; bc[3*i+1] = cl; bc[3*i+2] = ci;
    }
    size_t off = (size_t)m * KS + 3*k;       // 3k multiple of 24 -> 48B aligned
    uint4* ph = reinterpret_cast<uint4*>(&g_ahl[0][off]);
    uint4* pc = reinterpret_cast<uint4*>(&g_ahl[1][off]);
    const uint4* sh = reinterpret_cast<const uint4*>(bh);
    const uint4* sc = reinterpret_cast<const uint4*>(bc);
    ph[0] = sh[0]; ph[1] = sh[1]; ph[2] = sh[2];
    pc[0] = sc[0]; pc[1] = sc[1]; pc[2] = sc[2];
}

// ---------------------------------------------------------------------------
// 1b) W -> 3-term split; W-side pattern per element: [hi, hi, lo]
// ---------------------------------------------------------------------------
__global__ void split_w_kernel(const float4* __restrict__ Wq,
                               const float4* __restrict__ Wk,
                               const float4* __restrict__ Wv) {
    int idx = blockIdx.x * blockDim.x + threadIdx.x;   // group of 8 elements
    const int per = H_*H_/8;
    if (idx >= 3*per) return;
    int which = idx / per;
    int r = idx - which*per;
    const float4* W = (which == 0) ? Wq : (which == 1) ? Wk : Wv;
    float4 w0 = W[r*2], w1 = W[r*2+1];
    float wv[8] = {w0.x,w0.y,w0.z,w0.w, w1.x,w1.y,w1.z,w1.w};
    int e = r * 8;
    int n = e / H_, k = e % H_;

    __align__(16) __nv_bfloat16 bw[24];
    #pragma unroll
    for (int i = 0; i < 8; i++) {
        __nv_bfloat16 hi = __float2bfloat16(wv[i]);
        __nv_bfloat16 lo = __float2bfloat16(wv[i] - __bfloat162float(hi));
        bw[3*i] = hi; bw[3*i+1] = hi; bw[3*i+2] = lo;
    }
    uint4* pw = reinterpret_cast<uint4*>(&g_whl[which][(size_t)n * KS + 3*k]);
    const uint4* sw = reinterpret_cast<const uint4*>(bw);
    pw[0] = sw[0]; pw[1] = sw[1]; pw[2] = sw[2];
}

// ---------------------------------------------------------------------------
// 2) QKV via bf16 mma.sync, K'=2304. C = A W^T + bias, output (b,h,s,d).
//    CTA 128x128, 8 warps (2x4), warp tile 64x32, k-tile 32, cp.async 2-stage.
// ---------------------------------------------------------------------------
#define KT 32
#define STR 40   // smem row stride in bf16 (80B = 20 banks -> conflict-free frags)

__device__ __forceinline__ void cpasync16(void* dst, const void* src) {
    unsigned sa = (unsigned)__cvta_generic_to_shared(dst);
    asm volatile("cp.async.cg.shared.global [%0], [%1], 16;\n" :: "r"(sa), "l"(src));
}
__device__ __forceinline__ void mma_bf16(float* c, const unsigned* a, const unsigned* b) {
    asm volatile(
        "mma.sync.aligned.m16n8k16.row.col.f32.bf16.bf16.f32 "
        "{%0,%1,%2,%3},{%4,%5,%6,%7},{%8,%9},{%0,%1,%2,%3};"
        : "+f"(c[0]), "+f"(c[1]), "+f"(c[2]), "+f"(c[3])
        : "r"(a[0]), "r"(a[1]), "r"(a[2]), "r"(a[3]), "r"(b[0]), "r"(b[1]));
}

__global__ __launch_bounds__(256) void qkv_mma_kernel(
        const float* __restrict__ bq, const float* __restrict__ bk,
        const float* __restrict__ bv) {
    int which = blockIdx.z;
    const __nv_bfloat16* A  = g_ahl[which == 0 ? 0 : 1];
    const __nv_bfloat16* Bw = g_whl[which];
    const float* bias = (which == 0) ? bq : (which == 1) ? bk : bv;
    float* C          = (which == 0) ? g_q : (which == 1) ? g_k : g_v;

    __shared__ __nv_bfloat16 As[2][128*STR];
    __shared__ __nv_bfloat16 Bs[2][128*STR];

    int tid = threadIdx.x;
    int bm0 = blockIdx.x * 128;
    int bn0 = blockIdx.y * 128;

    int lr = tid >> 2;
    int lc = (tid & 3) * 8;
    const __nv_bfloat16* Ap0 = A  + (size_t)(bm0 + lr)      * KS + lc;
    const __nv_bfloat16* Ap1 = A  + (size_t)(bm0 + 64 + lr) * KS + lc;
    const __nv_bfloat16* Bp0 = Bw + (size_t)(bn0 + lr)      * KS + lc;
    const __nv_bfloat16* Bp1 = Bw + (size_t)(bn0 + 64 + lr) * KS + lc;

    #define LOAD_TILE(t, bf)                                            \
        cpasync16(&As[bf][lr*STR + lc],        Ap0 + (t)*KT);           \
        cpasync16(&As[bf][(lr+64)*STR + lc],   Ap1 + (t)*KT);           \
        cpasync16(&Bs[bf][lr*STR + lc],        Bp0 + (t)*KT);           \
        cpasync16(&Bs[bf][(lr+64)*STR + lc],   Bp1 + (t)*KT);           \
        asm volatile("cp.async.commit_group;\n");

    LOAD_TILE(0, 0);
    asm volatile("cp.async.wait_group 0;\n");
    __syncthreads();

    int lane = tid & 31, w = tid >> 5;
    int g  = lane >> 2, tg = lane & 3;
    int mw = (w & 1) * 64;
    int nw = (w >> 1) * 32;

    float acc[4][4][4];
    #pragma unroll
    for (int i = 0; i < 4; i++)
        #pragma unroll
        for (int j = 0; j < 4; j++)
            #pragma unroll
            for (int r = 0; r < 4; r++) acc[i][j][r] = 0.f;

    const int NT = KS / KT;   // 72
    for (int t = 0; t < NT; t++) {
        int cur = t & 1;
        if (t + 1 < NT) { LOAD_TILE(t + 1, cur ^ 1); }

        #pragma unroll
        for (int kk = 0; kk < 2; kk++) {
            unsigned af[4][4], bfr[4][2];
            #pragma unroll
            for (int mi = 0; mi < 4; mi++) {
                const __nv_bfloat16* p = &As[cur][(mw + mi*16 + g)*STR + kk*16 + tg*2];
                af[mi][0] = *reinterpret_cast<const unsigned*>(p);
                af[mi][1] = *reinterpret_cast<const unsigned*>(p + 8*STR);
                af[mi][2] = *reinterpret_cast<const unsigned*>(p + 8);
                af[mi][3] = *reinterpret_cast<const unsigned*>(p + 8*STR + 8);
            }
            #pragma unroll
            for (int ni = 0; ni < 4; ni++) {
                const __nv_bfloat16* p = &Bs[cur][(nw + ni*8 + g)*STR + kk*16 + tg*2];
                bfr[ni][0] = *reinterpret_cast<const unsigned*>(p);
                bfr[ni][1] = *reinterpret_cast<const unsigned*>(p + 8);
            }
            #pragma unroll
            for (int mi = 0; mi < 4; mi++)
                #pragma unroll
                for (int ni = 0; ni < 4; ni++)
                    mma_bf16(acc[mi][ni], af[mi], bfr[ni]);
        }
        asm volatile("cp.async.wait_group 0;\n");
        __syncthreads();
    }

    #pragma unroll
    for (int ni = 0; ni < 4; ni++) {
        int n = bn0 + nw + ni*8 + tg*2;
        int h = n >> 6, d = n & 63;
        float2 bb = *reinterpret_cast<const float2*>(bias + n);
        #pragma unroll
        for (int mi = 0; mi < 4; mi++) {
            int m = bm0 + mw + mi*16 + g;
            int b = m >> 10, s = m & 1023;
            float2 o0 = make_float2(acc[mi][ni][0] + bb.x, acc[mi][ni][1] + bb.y);
            *reinterpret_cast<float2*>(
                C + (((size_t)(b*NH_ + h) * S_ + s) * DH_ + d)) = o0;
            int m2 = m + 8, s2 = m2 & 1023;
            float2 o1 = make_float2(acc[mi][ni][2] + bb.x, acc[mi][ni][3] + bb.y);
            *reinterpret_cast<float2*>(
                C + (((size_t)(b*NH_ + h) * S_ + s2) * DH_ + d)) = o1;
        }
    }
}

// ---------------------------------------------------------------------------
// 3) scores[b,h,q,k]: NEG for masked entries, else (q.k)/8 * gate + amask
// ---------------------------------------------------------------------------
__global__ __launch_bounds__(256) void scores_kernel(
        const float* __restrict__ gate, const float* __restrict__ amask,
        const int* __restrict__ feat_len, const int* __restrict__ ppos,
        float* __restrict__ scores) {
    int q  = blockIdx.x;
    int bh = blockIdx.y;
    int b  = bh / NH_;
    int P  = ppos ? ppos[0] : 512;
    int fl = feat_len[b];

    __shared__ float qrow[DH_];
    if (threadIdx.x < DH_)
        qrow[threadIdx.x] = g_q[((size_t)bh * S_ + q) * DH_ + threadIdx.x];
    __syncthreads();

    int k0 = threadIdx.x * 4;
    float res[4];
    #pragma unroll
    for (int j = 0; j < 4; j++) {
        int k = k0 + j;
        bool masked;
        if      (q <  P-1) masked = (k > q) || (k < q-1);
        else if (q == P-1) masked = false;
        else               masked = (k >= P) || (k < fl-1);
        if (masked) {
            res[j] = NEGV;
        } else {
            const float4* kp = reinterpret_cast<const float4*>(
                g_k + ((size_t)bh * S_ + k) * DH_);
            float dot = 0.f;
            #pragma unroll
            for (int d4 = 0; d4 < DH_/4; d4++) {
                float4 kv = __ldg(&kp[d4]);
                dot += qrow[d4*4+0]*kv.x + qrow[d4*4+1]*kv.y
                     + qrow[d4*4+2]*kv.z + qrow[d4*4+3]*kv.w;
            }
            res[j] = dot * 0.125f * gate[((size_t)b * S_ + q) * S_ + k]
                   + amask[b * S_ + k];
        }
    }
    float4 o = make_float4(res[0], res[1], res[2], res[3]);
    *reinterpret_cast<float4*>(scores + ((size_t)bh * S_ + q) * S_ + k0) = o;
}

// ---------------------------------------------------------------------------
// 4a) Rows q < P-1: only k in {q-1, q} survive. out = softmax2 . v
// ---------------------------------------------------------------------------
__global__ void softmax_sparse_kernel(const float* __restrict__ scores,
                                      const int* __restrict__ ppos,
                                      float* __restrict__ out) {
    int tid = threadIdx.x;
    int R = blockIdx.x * 4 + (tid >> 6);
    int d = tid & 63;
    int bh = R >> 10;
    int q  = R & 1023;
    int P  = ppos ? ppos[0] : 512;
    if (q >= P-1) return;
    int b = bh / NH_, h = bh % NH_;
    const float* srow = scores + (size_t)R * S_;

    float val;
    if (q == 0) {
        val = g_v[((size_t)bh * S_) * DH_ + d];
    } else {
        float s0 = srow[q-1], s1 = srow[q];
        float m = fmaxf(s0, s1);
        float p0 = expf(s0 - m), p1 = expf(s1 - m);
        float inv = 1.f / (p0 + p1);
        val = (p0 * g_v[((size_t)bh*S_ + q-1)*DH_ + d]
             + p1 * g_v[((size_t)bh*S_ + q  )*DH_ + d]) * inv;
    }
    out[((size_t)(b*S_ + q)) * H_ + h*DH_ + d] = val;
}

// ---------------------------------------------------------------------------
// 4b) Rows q >= P-1: tiled softmax+PV, per-row spans.
// ---------------------------------------------------------------------------
#define QT 32
#define KTILE 64
__global__ __launch_bounds__(256) void pv_tiled_kernel(
        const float* __restrict__ scores, const int* __restrict__ feat_len,
        const int* __restrict__ ppos, float* __restrict__ out) {
    int bh = blockIdx.y;
    int b = bh / NH_, h = bh % NH_;
    int P = ppos ? ppos[0] : 512;
    int q0 = blockIdx.x * QT;
    if (q0 + QT <= P-1) return;
    int fl = feat_len[b];
    int lo0 = max(0, fl - 1), hi0 = P;
    if (lo0 >= hi0) { lo0 = 0; hi0 = S_; }

    bool hasPm1 = (P-1 >= q0) && (P-1 < q0 + QT);
    bool hasGE  = (q0 + QT - 1 >= P);
    int ulo = hasPm1 ? 0 : lo0;
    int uhi = hasPm1 ? S_ : hi0;
    if (hasPm1 && hasGE) { ulo = min(0, lo0); uhi = max(S_, hi0); }
    if (hasGE && !hasPm1) { ulo = lo0; uhi = hi0; }

    __shared__ float Vs[KTILE][DH_ + 4];
    __shared__ float Ps[QT][KTILE];
    __shared__ float Ms[QT], Is[QT];

    int tid = threadIdx.x;
    int w = tid >> 5, lane = tid & 31;

    for (int rr = 0; rr < 4; rr++) {
        int r = w*4 + rr;
        int q = q0 + r;
        if (q < P-1) continue;
        int rlo = (q == P-1) ? 0  : lo0;
        int rhi = (q == P-1) ? S_ : hi0;
        const float* srow = scores + ((size_t)bh * S_ + q) * S_;
        float m = -INFINITY;
        for (int k = rlo + lane; k < rhi; k += 32) m = fmaxf(m, srow[k]);
        #pragma unroll
        for (int off = 16; off > 0; off >>= 1)
            m = fmaxf(m, __shfl_xor_sync(0xffffffffu, m, off));
        float s = 0.f;
        for (int k = rlo + lane; k < rhi; k += 32) s += expf(srow[k] - m);
        #pragma unroll
        for (int off = 16; off > 0; off >>= 1)
            s += __shfl_xor_sync(0xffffffffu, s, off);
        if (lane == 0) { Ms[r] = m; Is[r] = 1.f / s; }
    }
    __syncthreads();

    int d = tid & 63;
    int g = tid >> 6;
    float acc[8];
    #pragma unroll
    for (int j = 0; j < 8; j++) acc[j] = 0.f;

    int pr  = tid >> 3;
    int pq  = q0 + pr;
    int pk0 = (tid & 7) * 8;
    bool pact = (pq >= P-1);
    int prlo = (pq == P-1) ? 0  : lo0;
    int prhi = (pq == P-1) ? S_ : hi0;
    float pM = 0.f, pI = 0.f;
    if (pact) { pM = Ms[pr]; pI = Is[pr]; }
    const float* psrow = scores + ((size_t)bh * S_ + pq) * S_;

    for (int kt = ulo; kt < uhi; kt += KTILE) {
        __syncthreads();
        #pragma unroll
        for (int it = 0; it < 4; it++) {
            int idx = tid + it * 256;
            int r = idx >> 4, c4 = (idx & 15) * 4;
            float4 v4 = make_float4(0.f, 0.f, 0.f, 0.f);
            if (kt + r < uhi)
                v4 = *reinterpret_cast<const float4*>(
                    g_v + ((size_t)bh * S_ + kt + r) * DH_ + c4);
            *reinterpret_cast<float4*>(&Vs[r][c4]) = v4;
        }
        #pragma unroll
        for (int j = 0; j < 8; j++) {
            int k = kt + pk0 + j;
            float p = 0.f;
            if (pact && k >= prlo && k < prhi) p = expf(psrow[k] - pM) * pI;
            Ps[pr][pk0 + j] = p;
        }
        __syncthreads();
        #pragma unroll 8
        for (int kk = 0; kk < KTILE; kk++) {
            float vv = Vs[kk][d];
            #pragma unroll
            for (int j = 0; j < 8; j++)
                acc[j] += Ps[g*8 + j][kk] * vv;
        }
    }

    #pragma unroll
    for (int j = 0; j < 8; j++) {
        int q = q0 + g*8 + j;
        if (q >= P-1)
            out[((size_t)(b*S_ + q)) * H_ + h*DH_ + d] = acc[j];
    }
}

// ---------------------------------------------------------------------------
extern "C" void kernel_launch(void* const* d_in, const int* in_sizes, int n_in,
                              void* d_out, int out_size) {
    const float* hidden  = (const float*)d_in[0];
    const float* context = (const float*)d_in[1];
    const float* amask   = (const float*)d_in[2];
    const float* gate    = (const float*)d_in[3];
    const float* vis     = (const float*)d_in[4];
    const float* Wq      = (const float*)d_in[5];
    const float* bq      = (const float*)d_in[6];
    const float* Wk      = (const float*)d_in[7];
    const float* bk      = (const float*)d_in[8];
    const float* Wv      = (const float*)d_in[9];
    const float* bv      = (const float*)d_in[10];
    const int*   feat_len= (const int*)  d_in[11];
    const int*   ppos    = (n_in > 12) ? (const int*)d_in[12] : nullptr;

    float* out    = (float*)d_out;                       // (B,S,H)
    float* scores = out + (size_t)B_ * S_ * H_;          // (B,NH,S,S)

    split_a_kernel<<<(B_*S_*H_/8 + 255)/256, 256>>>(
        (const float4*)hidden, (const float4*)context,
        (const float4*)vis, feat_len);
    split_w_kernel<<<(3*H_*H_/8 + 255)/256, 256>>>(
        (const float4*)Wq, (const float4*)Wk, (const float4*)Wv);

    dim3 gg((B_*S_)/128, H_/128, 3);
    qkv_mma_kernel<<<gg, 256>>>(bq, bk, bv);

    scores_kernel<<<dim3(S_, B_*NH_), 256>>>(gate, amask, feat_len, ppos, scores);

    softmax_sparse_kernel<<<(B_*NH_*S_)/4, 256>>>(scores, ppos, out);
    pv_tiled_kernel<<<dim3(S_/QT, B_*NH_), 256>>>(scores, feat_len, ppos, out);
}

// round 7
// speedup vs baseline: 2.4865x; 1.5178x over previous
#include <cuda_runtime.h>
#include <cuda_bf16.h>
#include <math.h>

#define B_  4
#define S_  1024
#define H_  768
#define NH_ 12
#define DH_ 64
#define NEGV -100000.0f
#define KS  2304              // 3-term split: per k -> [ah, al, ah] x [wh, wh, wl]

// Scratch (allocation-free rule: __device__ globals)
__device__ __nv_bfloat16 g_ahl[2][(size_t)B_*S_*KS]; // 0: hs split, 1: ctx split
__device__ __nv_bfloat16 g_whl[3][(size_t)H_*KS];    // Wq/Wk/Wv split
__device__ float g_q[B_*S_*H_];   // (b,h,s,d)
__device__ float g_k[B_*S_*H_];
__device__ float g_v[B_*S_*H_];

// ---------------------------------------------------------------------------
// 1) Fused: hs/ctx = input + masked vis, then fp32 -> 3-term bf16 split.
// ---------------------------------------------------------------------------
__global__ void split_a_kernel(const float4* __restrict__ hidden,
                               const float4* __restrict__ context,
                               const float4* __restrict__ vis,
                               const int*    __restrict__ feat_len) {
    int idx = blockIdx.x * blockDim.x + threadIdx.x;   // group of 8 elements
    const int ng = B_*S_*H_/8;
    if (idx >= ng) return;
    int e = idx * 8;
    int m = e / H_;
    int k = e % H_;
    int b = m >> 10;
    int s = m & 1023;

    float4 h0 = hidden[idx*2], h1 = hidden[idx*2+1];
    float4 c0 = context[idx*2], c1 = context[idx*2+1];
    float hv[8] = {h0.x,h0.y,h0.z,h0.w, h1.x,h1.y,h1.z,h1.w};
    float cv[8] = {c0.x,c0.y,c0.z,c0.w, c1.x,c1.y,c1.z,c1.w};
    if (s < feat_len[b]) {
        float4 a0 = vis[idx*2], a1 = vis[idx*2+1];
        float av[8] = {a0.x,a0.y,a0.z,a0.w, a1.x,a1.y,a1.z,a1.w};
        #pragma unroll
        for (int i = 0; i < 8; i++) { hv[i] += av[i]; cv[i] += av[i]; }
    }

    __align__(16) __nv_bfloat16 bh[24], bc[24];
    #pragma unroll
    for (int i = 0; i < 8; i++) {
        __nv_bfloat16 hi = __float2bfloat16(hv[i]);
        __nv_bfloat16 lo = __float2bfloat16(hv[i] - __bfloat162float(hi));
        bh[3*i] = hi; bh[3*i+1] = lo; bh[3*i+2] = hi;
        __nv_bfloat16 ci = __float2bfloat16(cv[i]);
        __nv_bfloat16 cl = __float2bfloat16(cv[i] - __bfloat162float(ci));
        bc[3*i] = ci; bc[3*i+1] = cl; bc[3*i+2] = ci;
    }
    size_t off = (size_t)m * KS + 3*k;
    uint4* ph = reinterpret_cast<uint4*>(&g_ahl[0][off]);
    uint4* pc = reinterpret_cast<uint4*>(&g_ahl[1][off]);
    const uint4* sh = reinterpret_cast<const uint4*>(bh);
    const uint4* sc = reinterpret_cast<const uint4*>(bc);
    ph[0] = sh[0]; ph[1] = sh[1]; ph[2] = sh[2];
    pc[0] = sc[0]; pc[1] = sc[1]; pc[2] = sc[2];
}

// ---------------------------------------------------------------------------
// 1b) W -> 3-term split; W-side pattern per element: [hi, hi, lo]
// ---------------------------------------------------------------------------
__global__ void split_w_kernel(const float4* __restrict__ Wq,
                               const float4* __restrict__ Wk,
                               const float4* __restrict__ Wv) {
    int idx = blockIdx.x * blockDim.x + threadIdx.x;
    const int per = H_*H_/8;
    if (idx >= 3*per) return;
    int which = idx / per;
    int r = idx - which*per;
    const float4* W = (which == 0) ? Wq : (which == 1) ? Wk : Wv;
    float4 w0 = W[r*2], w1 = W[r*2+1];
    float wv[8] = {w0.x,w0.y,w0.z,w0.w, w1.x,w1.y,w1.z,w1.w};
    int e = r * 8;
    int n = e / H_, k = e % H_;

    __align__(16) __nv_bfloat16 bw[24];
    #pragma unroll
    for (int i = 0; i < 8; i++) {
        __nv_bfloat16 hi = __float2bfloat16(wv[i]);
        __nv_bfloat16 lo = __float2bfloat16(wv[i] - __bfloat162float(hi));
        bw[3*i] = hi; bw[3*i+1] = hi; bw[3*i+2] = lo;
    }
    uint4* pw = reinterpret_cast<uint4*>(&g_whl[which][(size_t)n * KS + 3*k]);
    const uint4* sw = reinterpret_cast<const uint4*>(bw);
    pw[0] = sw[0]; pw[1] = sw[1]; pw[2] = sw[2];
}

// ---------------------------------------------------------------------------
// 2) QKV via bf16 mma.sync, K'=2304.
// ---------------------------------------------------------------------------
#define KT 32
#define STR 40

__device__ __forceinline__ void cpasync16(void* dst, const void* src) {
    unsigned sa = (unsigned)__cvta_generic_to_shared(dst);
    asm volatile("cp.async.cg.shared.global [%0], [%1], 16;\n" :: "r"(sa), "l"(src));
}
__device__ __forceinline__ void mma_bf16(float* c, const unsigned* a, const unsigned* b) {
    asm volatile(
        "mma.sync.aligned.m16n8k16.row.col.f32.bf16.bf16.f32 "
        "{%0,%1,%2,%3},{%4,%5,%6,%7},{%8,%9},{%0,%1,%2,%3};"
        : "+f"(c[0]), "+f"(c[1]), "+f"(c[2]), "+f"(c[3])
        : "r"(a[0]), "r"(a[1]), "r"(a[2]), "r"(a[3]), "r"(b[0]), "r"(b[1]));
}

__global__ __launch_bounds__(256) void qkv_mma_kernel(
        const float* __restrict__ bq, const float* __restrict__ bk,
        const float* __restrict__ bv) {
    int which = blockIdx.z;
    const __nv_bfloat16* A  = g_ahl[which == 0 ? 0 : 1];
    const __nv_bfloat16* Bw = g_whl[which];
    const float* bias = (which == 0) ? bq : (which == 1) ? bk : bv;
    float* C          = (which == 0) ? g_q : (which == 1) ? g_k : g_v;

    __shared__ __nv_bfloat16 As[2][128*STR];
    __shared__ __nv_bfloat16 Bs[2][128*STR];

    int tid = threadIdx.x;
    int bm0 = blockIdx.x * 128;
    int bn0 = blockIdx.y * 128;

    int lr = tid >> 2;
    int lc = (tid & 3) * 8;
    const __nv_bfloat16* Ap0 = A  + (size_t)(bm0 + lr)      * KS + lc;
    const __nv_bfloat16* Ap1 = A  + (size_t)(bm0 + 64 + lr) * KS + lc;
    const __nv_bfloat16* Bp0 = Bw + (size_t)(bn0 + lr)      * KS + lc;
    const __nv_bfloat16* Bp1 = Bw + (size_t)(bn0 + 64 + lr) * KS + lc;

    #define LOAD_TILE(t, bf)                                            \
        cpasync16(&As[bf][lr*STR + lc],        Ap0 + (t)*KT);           \
        cpasync16(&As[bf][(lr+64)*STR + lc],   Ap1 + (t)*KT);           \
        cpasync16(&Bs[bf][lr*STR + lc],        Bp0 + (t)*KT);           \
        cpasync16(&Bs[bf][(lr+64)*STR + lc],   Bp1 + (t)*KT);           \
        asm volatile("cp.async.commit_group;\n");

    LOAD_TILE(0, 0);
    asm volatile("cp.async.wait_group 0;\n");
    __syncthreads();

    int lane = tid & 31, w = tid >> 5;
    int g  = lane >> 2, tg = lane & 3;
    int mw = (w & 1) * 64;
    int nw = (w >> 1) * 32;

    float acc[4][4][4];
    #pragma unroll
    for (int i = 0; i < 4; i++)
        #pragma unroll
        for (int j = 0; j < 4; j++)
            #pragma unroll
            for (int r = 0; r < 4; r++) acc[i][j][r] = 0.f;

    const int NT = KS / KT;   // 72
    for (int t = 0; t < NT; t++) {
        int cur = t & 1;
        if (t + 1 < NT) { LOAD_TILE(t + 1, cur ^ 1); }

        #pragma unroll
        for (int kk = 0; kk < 2; kk++) {
            unsigned af[4][4], bfr[4][2];
            #pragma unroll
            for (int mi = 0; mi < 4; mi++) {
                const __nv_bfloat16* p = &As[cur][(mw + mi*16 + g)*STR + kk*16 + tg*2];
                af[mi][0] = *reinterpret_cast<const unsigned*>(p);
                af[mi][1] = *reinterpret_cast<const unsigned*>(p + 8*STR);
                af[mi][2] = *reinterpret_cast<const unsigned*>(p + 8);
                af[mi][3] = *reinterpret_cast<const unsigned*>(p + 8*STR + 8);
            }
            #pragma unroll
            for (int ni = 0; ni < 4; ni++) {
                const __nv_bfloat16* p = &Bs[cur][(nw + ni*8 + g)*STR + kk*16 + tg*2];
                bfr[ni][0] = *reinterpret_cast<const unsigned*>(p);
                bfr[ni][1] = *reinterpret_cast<const unsigned*>(p + 8);
            }
            #pragma unroll
            for (int mi = 0; mi < 4; mi++)
                #pragma unroll
                for (int ni = 0; ni < 4; ni++)
                    mma_bf16(acc[mi][ni], af[mi], bfr[ni]);
        }
        asm volatile("cp.async.wait_group 0;\n");
        __syncthreads();
    }

    #pragma unroll
    for (int ni = 0; ni < 4; ni++) {
        int n = bn0 + nw + ni*8 + tg*2;
        int h = n >> 6, d = n & 63;
        float2 bb = *reinterpret_cast<const float2*>(bias + n);
        #pragma unroll
        for (int mi = 0; mi < 4; mi++) {
            int m = bm0 + mw + mi*16 + g;
            int b = m >> 10, s = m & 1023;
            float2 o0 = make_float2(acc[mi][ni][0] + bb.x, acc[mi][ni][1] + bb.y);
            *reinterpret_cast<float2*>(
                C + (((size_t)(b*NH_ + h) * S_ + s) * DH_ + d)) = o0;
            int m2 = m + 8, s2 = m2 & 1023;
            float2 o1 = make_float2(acc[mi][ni][2] + bb.x, acc[mi][ni][3] + bb.y);
            *reinterpret_cast<float2*>(
                C + (((size_t)(b*NH_ + h) * S_ + s2) * DH_ + d)) = o1;
        }
    }
}

// ---------------------------------------------------------------------------
// 3a) Band rows q < P-1: NEG everywhere except k in {q-1, q}.
// ---------------------------------------------------------------------------
__global__ __launch_bounds__(256) void scores_band_kernel(
        const float* __restrict__ gate, const float* __restrict__ amask,
        const int* __restrict__ ppos, float* __restrict__ scores) {
    int q  = blockIdx.x;
    int bh = blockIdx.y;
    int P  = ppos ? ppos[0] : 512;
    if (q >= P-1) return;
    int b  = bh / NH_;

    __shared__ float qrow[DH_];
    if (threadIdx.x < DH_)
        qrow[threadIdx.x] = g_q[((size_t)bh * S_ + q) * DH_ + threadIdx.x];
    __syncthreads();

    int k0 = threadIdx.x * 4;
    float res[4];
    #pragma unroll
    for (int j = 0; j < 4; j++) {
        int k = k0 + j;
        if (k > q || k < q-1) {
            res[j] = NEGV;
        } else {
            const float4* kp = reinterpret_cast<const float4*>(
                g_k + ((size_t)bh * S_ + k) * DH_);
            float dot = 0.f;
            #pragma unroll
            for (int d4 = 0; d4 < DH_/4; d4++) {
                float4 kv = __ldg(&kp[d4]);
                dot += qrow[d4*4+0]*kv.x + qrow[d4*4+1]*kv.y
                     + qrow[d4*4+2]*kv.z + qrow[d4*4+3]*kv.w;
            }
            res[j] = dot * 0.125f * gate[((size_t)b * S_ + q) * S_ + k]
                   + amask[b * S_ + k];
        }
    }
    float4 o = make_float4(res[0], res[1], res[2], res[3]);
    *reinterpret_cast<float4*>(scores + ((size_t)bh * S_ + q) * S_ + k0) = o;
}

// ---------------------------------------------------------------------------
// 3b) Dense rows q >= P-1: tiled 64x64 GEMM with NEG fast paths.
//     Row P-1: fully unmasked. Rows >= P: unmasked iff fl-1 <= k < P.
// ---------------------------------------------------------------------------
__global__ __launch_bounds__(256) void scores_dense_kernel(
        const float* __restrict__ gate, const float* __restrict__ amask,
        const int* __restrict__ feat_len, const int* __restrict__ ppos,
        float* __restrict__ scores) {
    int kt = blockIdx.x, qt = blockIdx.y, bh = blockIdx.z;
    int b = bh / NH_;
    int P = ppos ? ppos[0] : 512;
    int q0 = qt * 64, k0 = kt * 64;
    if (q0 + 63 < P - 1) return;               // no rows >= P-1 in tile
    int fl = feat_len[b];
    int lo0 = max(0, fl - 1), hi0 = P;
    bool hasPm1 = (P-1 >= q0) && (P-1 < q0 + 64);
    bool spanOv = (lo0 < hi0) && (k0 < hi0) && (k0 + 64 > lo0) && (q0 + 63 >= P);
    int tid = threadIdx.x;

    if (!hasPm1 && !spanOv) {
        // every row >= P-1 in this tile is fully masked on [k0, k0+64)
        float4 neg4 = make_float4(NEGV, NEGV, NEGV, NEGV);
        int kc = k0 + (tid & 15) * 4;
        #pragma unroll
        for (int it = 0; it < 4; it++) {
            int q = q0 + (tid >> 4) + it * 16;
            if (q >= P-1)
                *reinterpret_cast<float4*>(
                    scores + ((size_t)bh * S_ + q) * S_ + kc) = neg4;
        }
        return;
    }

    if (hasPm1 && !spanOv) {
        // only live row is P-1: warp-cooperative dots (4 threads per k)
        int q = P - 1;
        int kk = tid >> 2;
        int dc = (tid & 3) * 16;
        const float4* qp = reinterpret_cast<const float4*>(
            g_q + ((size_t)bh * S_ + q) * DH_ + dc);
        const float4* kp = reinterpret_cast<const float4*>(
            g_k + ((size_t)bh * S_ + k0 + kk) * DH_ + dc);
        float part = 0.f;
        #pragma unroll
        for (int i = 0; i < 4; i++) {
            float4 a = qp[i], v = kp[i];
            part += a.x*v.x + a.y*v.y + a.z*v.z + a.w*v.w;
        }
        part += __shfl_xor_sync(0xffffffffu, part, 1);
        part += __shfl_xor_sync(0xffffffffu, part, 2);
        if ((tid & 3) == 0) {
            int k = k0 + kk;
            scores[((size_t)bh * S_ + q) * S_ + k] =
                part * 0.125f * gate[((size_t)b * S_ + q) * S_ + k] + amask[b * S_ + k];
        }
        // NEG-fill rows >= P in tile (fully masked here)
        float4 neg4 = make_float4(NEGV, NEGV, NEGV, NEGV);
        int kc = k0 + (tid & 15) * 4;
        #pragma unroll
        for (int it = 0; it < 4; it++) {
            int q2 = q0 + (tid >> 4) + it * 16;
            if (q2 >= P)
                *reinterpret_cast<float4*>(
                    scores + ((size_t)bh * S_ + q2) * S_ + kc) = neg4;
        }
        return;
    }

    // Full tile GEMM: Qs/Ks transposed [d][idx], 16x16 threads x 4x4 outputs
    __shared__ float Qs[DH_][68];
    __shared__ float Ks[DH_][68];
    #pragma unroll
    for (int it = 0; it < 4; it++) {
        int idx = tid + it * 256;
        int r = idx >> 4, c4 = (idx & 15) * 4;
        float4 qv = *reinterpret_cast<const float4*>(
            g_q + ((size_t)bh * S_ + q0 + r) * DH_ + c4);
        float4 kv = *reinterpret_cast<const float4*>(
            g_k + ((size_t)bh * S_ + k0 + r) * DH_ + c4);
        Qs[c4+0][r] = qv.x; Qs[c4+1][r] = qv.y; Qs[c4+2][r] = qv.z; Qs[c4+3][r] = qv.w;
        Ks[c4+0][r] = kv.x; Ks[c4+1][r] = kv.y; Ks[c4+2][r] = kv.z; Ks[c4+3][r] = kv.w;
    }
    __syncthreads();

    int tq = tid >> 4, tk = tid & 15;
    float acc[4][4];
    #pragma unroll
    for (int i = 0; i < 4; i++)
        #pragma unroll
        for (int j = 0; j < 4; j++) acc[i][j] = 0.f;

    #pragma unroll 4
    for (int d = 0; d < DH_; d++) {
        float4 qv = *reinterpret_cast<float4*>(&Qs[d][tq*4]);
        float4 kv = *reinterpret_cast<float4*>(&Ks[d][tk*4]);
        float qa[4] = {qv.x, qv.y, qv.z, qv.w};
        float ka[4] = {kv.x, kv.y, kv.z, kv.w};
        #pragma unroll
        for (int i = 0; i < 4; i++)
            #pragma unroll
            for (int j = 0; j < 4; j++)
                acc[i][j] += qa[i] * ka[j];
    }

    #pragma unroll
    for (int i = 0; i < 4; i++) {
        int q = q0 + tq*4 + i;
        if (q < P-1) continue;                 // band kernel owns these
        bool full = (q == P-1);
        float res[4];
        #pragma unroll
        for (int j = 0; j < 4; j++) {
            int k = k0 + tk*4 + j;
            bool masked = !full && ((k >= P) || (k < fl-1));
            res[j] = masked ? NEGV
                   : acc[i][j] * 0.125f * gate[((size_t)b * S_ + q) * S_ + k]
                     + amask[b * S_ + k];
        }
        *reinterpret_cast<float4*>(
            scores + ((size_t)bh * S_ + q) * S_ + k0 + tk*4)
            = make_float4(res[0], res[1], res[2], res[3]);
    }
}

// ---------------------------------------------------------------------------
// 4a) Rows q < P-1: only k in {q-1, q} survive. out = softmax2 . v
// ---------------------------------------------------------------------------
__global__ void softmax_sparse_kernel(const float* __restrict__ scores,
                                      const int* __restrict__ ppos,
                                      float* __restrict__ out) {
    int tid = threadIdx.x;
    int R = blockIdx.x * 4 + (tid >> 6);
    int d = tid & 63;
    int bh = R >> 10;
    int q  = R & 1023;
    int P  = ppos ? ppos[0] : 512;
    if (q >= P-1) return;
    int b = bh / NH_, h = bh % NH_;
    const float* srow = scores + (size_t)R * S_;

    float val;
    if (q == 0) {
        val = g_v[((size_t)bh * S_) * DH_ + d];
    } else {
        float s0 = srow[q-1], s1 = srow[q];
        float m = fmaxf(s0, s1);
        float p0 = expf(s0 - m), p1 = expf(s1 - m);
        float inv = 1.f / (p0 + p1);
        val = (p0 * g_v[((size_t)bh*S_ + q-1)*DH_ + d]
             + p1 * g_v[((size_t)bh*S_ + q  )*DH_ + d]) * inv;
    }
    out[((size_t)(b*S_ + q)) * H_ + h*DH_ + d] = val;
}

// ---------------------------------------------------------------------------
// 4b) Rows q >= P-1: tiled softmax+PV, per-row spans.
// ---------------------------------------------------------------------------
#define QT 32
#define KTILE 64
__global__ __launch_bounds__(256) void pv_tiled_kernel(
        const float* __restrict__ scores, const int* __restrict__ feat_len,
        const int* __restrict__ ppos, float* __restrict__ out) {
    int bh = blockIdx.y;
    int b = bh / NH_, h = bh % NH_;
    int P = ppos ? ppos[0] : 512;
    int q0 = blockIdx.x * QT;
    if (q0 + QT <= P-1) return;
    int fl = feat_len[b];
    int lo0 = max(0, fl - 1), hi0 = P;
    if (lo0 >= hi0) { lo0 = 0; hi0 = S_; }

    bool hasPm1 = (P-1 >= q0) && (P-1 < q0 + QT);
    bool hasGE  = (q0 + QT - 1 >= P);
    int ulo = hasPm1 ? 0 : lo0;
    int uhi = hasPm1 ? S_ : hi0;
    if (hasPm1 && hasGE) { ulo = min(0, lo0); uhi = max(S_, hi0); }
    if (hasGE && !hasPm1) { ulo = lo0; uhi = hi0; }

    __shared__ float Vs[KTILE][DH_ + 4];
    __shared__ float Ps[QT][KTILE];
    __shared__ float Ms[QT], Is[QT];

    int tid = threadIdx.x;
    int w = tid >> 5, lane = tid & 31;

    for (int rr = 0; rr < 4; rr++) {
        int r = w*4 + rr;
        int q = q0 + r;
        if (q < P-1) continue;
        int rlo = (q == P-1) ? 0  : lo0;
        int rhi = (q == P-1) ? S_ : hi0;
        const float* srow = scores + ((size_t)bh * S_ + q) * S_;
        float m = -INFINITY;
        for (int k = rlo + lane; k < rhi; k += 32) m = fmaxf(m, srow[k]);
        #pragma unroll
        for (int off = 16; off > 0; off >>= 1)
            m = fmaxf(m, __shfl_xor_sync(0xffffffffu, m, off));
        float s = 0.f;
        for (int k = rlo + lane; k < rhi; k += 32) s += expf(srow[k] - m);
        #pragma unroll
        for (int off = 16; off > 0; off >>= 1)
            s += __shfl_xor_sync(0xffffffffu, s, off);
        if (lane == 0) { Ms[r] = m; Is[r] = 1.f / s; }
    }
    __syncthreads();

    int d = tid & 63;
    int g = tid >> 6;
    float acc[8];
    #pragma unroll
    for (int j = 0; j < 8; j++) acc[j] = 0.f;

    int pr  = tid >> 3;
    int pq  = q0 + pr;
    int pk0 = (tid & 7) * 8;
    bool pact = (pq >= P-1);
    int prlo = (pq == P-1) ? 0  : lo0;
    int prhi = (pq == P-1) ? S_ : hi0;
    float pM = 0.f, pI = 0.f;
    if (pact) { pM = Ms[pr]; pI = Is[pr]; }
    const float* psrow = scores + ((size_t)bh * S_ + pq) * S_;

    for (int kt = ulo; kt < uhi; kt += KTILE) {
        __syncthreads();
        #pragma unroll
        for (int it = 0; it < 4; it++) {
            int idx = tid + it * 256;
            int r = idx >> 4, c4 = (idx & 15) * 4;
            float4 v4 = make_float4(0.f, 0.f, 0.f, 0.f);
            if (kt + r < uhi)
                v4 = *reinterpret_cast<const float4*>(
                    g_v + ((size_t)bh * S_ + kt + r) * DH_ + c4);
            *reinterpret_cast<float4*>(&Vs[r][c4]) = v4;
        }
        #pragma unroll
        for (int j = 0; j < 8; j++) {
            int k = kt + pk0 + j;
            float p = 0.f;
            if (pact && k >= prlo && k < prhi) p = expf(psrow[k] - pM) * pI;
            Ps[pr][pk0 + j] = p;
        }
        __syncthreads();
        #pragma unroll 8
        for (int kk = 0; kk < KTILE; kk++) {
            float vv = Vs[kk][d];
            #pragma unroll
            for (int j = 0; j < 8; j++)
                acc[j] += Ps[g*8 + j][kk] * vv;
        }
    }

    #pragma unroll
    for (int j = 0; j < 8; j++) {
        int q = q0 + g*8 + j;
        if (q >= P-1)
            out[((size_t)(b*S_ + q)) * H_ + h*DH_ + d] = acc[j];
    }
}

// ---------------------------------------------------------------------------
extern "C" void kernel_launch(void* const* d_in, const int* in_sizes, int n_in,
                              void* d_out, int out_size) {
    const float* hidden  = (const float*)d_in[0];
    const float* context = (const float*)d_in[1];
    const float* amask   = (const float*)d_in[2];
    const float* gate    = (const float*)d_in[3];
    const float* vis     = (const float*)d_in[4];
    const float* Wq      = (const float*)d_in[5];
    const float* bq      = (const float*)d_in[6];
    const float* Wk      = (const float*)d_in[7];
    const float* bk      = (const float*)d_in[8];
    const float* Wv      = (const float*)d_in[9];
    const float* bv      = (const float*)d_in[10];
    const int*   feat_len= (const int*)  d_in[11];
    const int*   ppos    = (n_in > 12) ? (const int*)d_in[12] : nullptr;

    float* out    = (float*)d_out;                       // (B,S,H)
    float* scores = out + (size_t)B_ * S_ * H_;          // (B,NH,S,S)

    split_a_kernel<<<(B_*S_*H_/8 + 255)/256, 256>>>(
        (const float4*)hidden, (const float4*)context,
        (const float4*)vis, feat_len);
    split_w_kernel<<<(3*H_*H_/8 + 255)/256, 256>>>(
        (const float4*)Wq, (const float4*)Wk, (const float4*)Wv);

    dim3 gg((B_*S_)/128, H_/128, 3);
    qkv_mma_kernel<<<gg, 256>>>(bq, bk, bv);

    scores_band_kernel<<<dim3(S_, B_*NH_), 256>>>(gate, amask, ppos, scores);
    scores_dense_kernel<<<dim3(S_/64, S_/64, B_*NH_), 256>>>(
        gate, amask, feat_len, ppos, scores);

    softmax_sparse_kernel<<<(B_*NH_*S_)/4, 256>>>(scores, ppos, out);
    pv_tiled_kernel<<<dim3(S_/QT, B_*NH_), 256>>>(scores, feat_len, ppos, out);
}

// round 9
// speedup vs baseline: 3.0447x; 1.2245x over previous
#include <cuda_runtime.h>
#include <cuda_bf16.h>
#include <math.h>

#define B_  4
#define S_  1024
#define H_  768
#define NH_ 12
#define DH_ 64
#define NEGV -100000.0f
#define KS  2304              // 3-term split: per k -> [ah, al, ah] x [wh, wh, wl]

// Scratch (allocation-free rule: __device__ globals)
__device__ __nv_bfloat16 g_ahl[2][(size_t)B_*S_*KS]; // 0: hs split, 1: ctx split
__device__ __nv_bfloat16 g_whl[3][(size_t)H_*KS];    // Wq/Wk/Wv split
__device__ float g_q[B_*S_*H_];   // (b,h,s,d)
__device__ float g_k[B_*S_*H_];
__device__ float g_v[B_*S_*H_];

// ---------------------------------------------------------------------------
// 1) Fused: hs/ctx = input + masked vis, then fp32 -> 3-term bf16 split.
// ---------------------------------------------------------------------------
__global__ void split_a_kernel(const float4* __restrict__ hidden,
                               const float4* __restrict__ context,
                               const float4* __restrict__ vis,
                               const int*    __restrict__ feat_len) {
    int idx = blockIdx.x * blockDim.x + threadIdx.x;   // group of 8 elements
    const int ng = B_*S_*H_/8;
    if (idx >= ng) return;
    int e = idx * 8;
    int m = e / H_;
    int k = e % H_;
    int b = m >> 10;
    int s = m & 1023;

    float4 h0 = hidden[idx*2], h1 = hidden[idx*2+1];
    float4 c0 = context[idx*2], c1 = context[idx*2+1];
    float hv[8] = {h0.x,h0.y,h0.z,h0.w, h1.x,h1.y,h1.z,h1.w};
    float cv[8] = {c0.x,c0.y,c0.z,c0.w, c1.x,c1.y,c1.z,c1.w};
    if (s < feat_len[b]) {
        float4 a0 = vis[idx*2], a1 = vis[idx*2+1];
        float av[8] = {a0.x,a0.y,a0.z,a0.w, a1.x,a1.y,a1.z,a1.w};
        #pragma unroll
        for (int i = 0; i < 8; i++) { hv[i] += av[i]; cv[i] += av[i]; }
    }

    __align__(16) __nv_bfloat16 bh[24], bc[24];
    #pragma unroll
    for (int i = 0; i < 8; i++) {
        __nv_bfloat16 hi = __float2bfloat16(hv[i]);
        __nv_bfloat16 lo = __float2bfloat16(hv[i] - __bfloat162float(hi));
        bh[3*i] = hi; bh[3*i+1] = lo; bh[3*i+2] = hi;
        __nv_bfloat16 ci = __float2bfloat16(cv[i]);
        __nv_bfloat16 cl = __float2bfloat16(cv[i] - __bfloat162float(ci));
        bc[3*i] = ci; bc[3*i+1] = cl; bc[3*i+2] = ci;
    }
    size_t off = (size_t)m * KS + 3*k;
    uint4* ph = reinterpret_cast<uint4*>(&g_ahl[0][off]);
    uint4* pc = reinterpret_cast<uint4*>(&g_ahl[1][off]);
    const uint4* sh = reinterpret_cast<const uint4*>(bh);
    const uint4* sc = reinterpret_cast<const uint4*>(bc);
    ph[0] = sh[0]; ph[1] = sh[1]; ph[2] = sh[2];
    pc[0] = sc[0]; pc[1] = sc[1]; pc[2] = sc[2];
}

// ---------------------------------------------------------------------------
// 1b) W -> 3-term split; W-side pattern per element: [hi, hi, lo]
// ---------------------------------------------------------------------------
__global__ void split_w_kernel(const float4* __restrict__ Wq,
                               const float4* __restrict__ Wk,
                               const float4* __restrict__ Wv) {
    int idx = blockIdx.x * blockDim.x + threadIdx.x;
    const int per = H_*H_/8;
    if (idx >= 3*per) return;
    int which = idx / per;
    int r = idx - which*per;
    const float4* W = (which == 0) ? Wq : (which == 1) ? Wk : Wv;
    float4 w0 = W[r*2], w1 = W[r*2+1];
    float wv[8] = {w0.x,w0.y,w0.z,w0.w, w1.x,w1.y,w1.z,w1.w};
    int e = r * 8;
    int n = e / H_, k = e % H_;

    __align__(16) __nv_bfloat16 bw[24];
    #pragma unroll
    for (int i = 0; i < 8; i++) {
        __nv_bfloat16 hi = __float2bfloat16(wv[i]);
        __nv_bfloat16 lo = __float2bfloat16(wv[i] - __bfloat162float(hi));
        bw[3*i] = hi; bw[3*i+1] = hi; bw[3*i+2] = lo;
    }
    uint4* pw = reinterpret_cast<uint4*>(&g_whl[which][(size_t)n * KS + 3*k]);
    const uint4* sw = reinterpret_cast<const uint4*>(bw);
    pw[0] = sw[0]; pw[1] = sw[1]; pw[2] = sw[2];
}

// ---------------------------------------------------------------------------
// 2) QKV via bf16 mma.sync, K'=2304 (unchanged).
// ---------------------------------------------------------------------------
#define KT 32
#define STR 40

__device__ __forceinline__ void cpasync16(void* dst, const void* src) {
    unsigned sa = (unsigned)__cvta_generic_to_shared(dst);
    asm volatile("cp.async.cg.shared.global [%0], [%1], 16;\n" :: "r"(sa), "l"(src));
}
__device__ __forceinline__ void mma_bf16(float* c, const unsigned* a, const unsigned* b) {
    asm volatile(
        "mma.sync.aligned.m16n8k16.row.col.f32.bf16.bf16.f32 "
        "{%0,%1,%2,%3},{%4,%5,%6,%7},{%8,%9},{%0,%1,%2,%3};"
        : "+f"(c[0]), "+f"(c[1]), "+f"(c[2]), "+f"(c[3])
        : "r"(a[0]), "r"(a[1]), "r"(a[2]), "r"(a[3]), "r"(b[0]), "r"(b[1]));
}

__global__ __launch_bounds__(256) void qkv_mma_kernel(
        const float* __restrict__ bq, const float* __restrict__ bk,
        const float* __restrict__ bv) {
    int which = blockIdx.z;
    const __nv_bfloat16* A  = g_ahl[which == 0 ? 0 : 1];
    const __nv_bfloat16* Bw = g_whl[which];
    const float* bias = (which == 0) ? bq : (which == 1) ? bk : bv;
    float* C          = (which == 0) ? g_q : (which == 1) ? g_k : g_v;

    __shared__ __nv_bfloat16 As[2][128*STR];
    __shared__ __nv_bfloat16 Bs[2][128*STR];

    int tid = threadIdx.x;
    int bm0 = blockIdx.x * 128;
    int bn0 = blockIdx.y * 128;

    int lr = tid >> 2;
    int lc = (tid & 3) * 8;
    const __nv_bfloat16* Ap0 = A  + (size_t)(bm0 + lr)      * KS + lc;
    const __nv_bfloat16* Ap1 = A  + (size_t)(bm0 + 64 + lr) * KS + lc;
    const __nv_bfloat16* Bp0 = Bw + (size_t)(bn0 + lr)      * KS + lc;
    const __nv_bfloat16* Bp1 = Bw + (size_t)(bn0 + 64 + lr) * KS + lc;

    #define LOAD_TILE(t, bf)                                            \
        cpasync16(&As[bf][lr*STR + lc],        Ap0 + (t)*KT);           \
        cpasync16(&As[bf][(lr+64)*STR + lc],   Ap1 + (t)*KT);           \
        cpasync16(&Bs[bf][lr*STR + lc],        Bp0 + (t)*KT);           \
        cpasync16(&Bs[bf][(lr+64)*STR + lc],   Bp1 + (t)*KT);           \
        asm volatile("cp.async.commit_group;\n");

    LOAD_TILE(0, 0);
    asm volatile("cp.async.wait_group 0;\n");
    __syncthreads();

    int lane = tid & 31, w = tid >> 5;
    int g  = lane >> 2, tg = lane & 3;
    int mw = (w & 1) * 64;
    int nw = (w >> 1) * 32;

    float acc[4][4][4];
    #pragma unroll
    for (int i = 0; i < 4; i++)
        #pragma unroll
        for (int j = 0; j < 4; j++)
            #pragma unroll
            for (int r = 0; r < 4; r++) acc[i][j][r] = 0.f;

    const int NT = KS / KT;   // 72
    for (int t = 0; t < NT; t++) {
        int cur = t & 1;
        if (t + 1 < NT) { LOAD_TILE(t + 1, cur ^ 1); }

        #pragma unroll
        for (int kk = 0; kk < 2; kk++) {
            unsigned af[4][4], bfr[4][2];
            #pragma unroll
            for (int mi = 0; mi < 4; mi++) {
                const __nv_bfloat16* p = &As[cur][(mw + mi*16 + g)*STR + kk*16 + tg*2];
                af[mi][0] = *reinterpret_cast<const unsigned*>(p);
                af[mi][1] = *reinterpret_cast<const unsigned*>(p + 8*STR);
                af[mi][2] = *reinterpret_cast<const unsigned*>(p + 8);
                af[mi][3] = *reinterpret_cast<const unsigned*>(p + 8*STR + 8);
            }
            #pragma unroll
            for (int ni = 0; ni < 4; ni++) {
                const __nv_bfloat16* p = &Bs[cur][(nw + ni*8 + g)*STR + kk*16 + tg*2];
                bfr[ni][0] = *reinterpret_cast<const unsigned*>(p);
                bfr[ni][1] = *reinterpret_cast<const unsigned*>(p + 8);
            }
            #pragma unroll
            for (int mi = 0; mi < 4; mi++)
                #pragma unroll
                for (int ni = 0; ni < 4; ni++)
                    mma_bf16(acc[mi][ni], af[mi], bfr[ni]);
        }
        asm volatile("cp.async.wait_group 0;\n");
        __syncthreads();
    }

    #pragma unroll
    for (int ni = 0; ni < 4; ni++) {
        int n = bn0 + nw + ni*8 + tg*2;
        int h = n >> 6, d = n & 63;
        float2 bb = *reinterpret_cast<const float2*>(bias + n);
        #pragma unroll
        for (int mi = 0; mi < 4; mi++) {
            int m = bm0 + mw + mi*16 + g;
            int b = m >> 10, s = m & 1023;
            float2 o0 = make_float2(acc[mi][ni][0] + bb.x, acc[mi][ni][1] + bb.y);
            *reinterpret_cast<float2*>(
                C + (((size_t)(b*NH_ + h) * S_ + s) * DH_ + d)) = o0;
            int m2 = m + 8, s2 = m2 & 1023;
            float2 o1 = make_float2(acc[mi][ni][2] + bb.x, acc[mi][ni][3] + bb.y);
            *reinterpret_cast<float2*>(
                C + (((size_t)(b*NH_ + h) * S_ + s2) * DH_ + d)) = o1;
        }
    }
}

// ---------------------------------------------------------------------------
// 3a-1) Pure NEG fill for band rows q < P-1 (max store bandwidth, no branches)
//       CTA covers 4 rows; thread writes 4 float4s.
// ---------------------------------------------------------------------------
__global__ __launch_bounds__(256) void band_fill_kernel(
        const int* __restrict__ ppos, float* __restrict__ scores) {
    int P = ppos ? ppos[0] : 512;
    int bh = blockIdx.y;
    int q  = blockIdx.x * 4 + (threadIdx.x >> 6);
    if (q >= P-1) return;
    int c = threadIdx.x & 63;
    float4 neg4 = make_float4(NEGV, NEGV, NEGV, NEGV);
    float4* row = reinterpret_cast<float4*>(scores + ((size_t)bh * S_ + q) * S_);
    #pragma unroll
    for (int i = 0; i < 4; i++)
        row[c + i*64] = neg4;
}

// ---------------------------------------------------------------------------
// 3a-2) Band dots: one warp per row; half-warp per live k in {q-1, q}.
//       Overwrites the 2 live entries written NEG by band_fill.
// ---------------------------------------------------------------------------
__global__ __launch_bounds__(256) void band_dots_kernel(
        const float* __restrict__ gate, const float* __restrict__ amask,
        const int* __restrict__ ppos, float* __restrict__ scores) {
    int P = ppos ? ppos[0] : 512;
    int wg = blockIdx.x * 8 + (threadIdx.x >> 5);
    int lane = threadIdx.x & 31;
    int bh = wg >> 10, q = wg & 1023;
    if (q >= P-1) return;                      // whole warp exits together
    int b = bh / NH_;
    int half = lane >> 4, t = lane & 15;
    int k = q - 1 + half;
    bool live = (k >= 0);
    float part = 0.f;
    if (live) {
        const float4* qp = reinterpret_cast<const float4*>(
            g_q + ((size_t)bh * S_ + q) * DH_);
        const float4* kp = reinterpret_cast<const float4*>(
            g_k + ((size_t)bh * S_ + k) * DH_);
        float4 a = qp[t], v = kp[t];
        part = a.x*v.x + a.y*v.y + a.z*v.z + a.w*v.w;
    }
    part += __shfl_xor_sync(0xffffffffu, part, 1);
    part += __shfl_xor_sync(0xffffffffu, part, 2);
    part += __shfl_xor_sync(0xffffffffu, part, 4);
    part += __shfl_xor_sync(0xffffffffu, part, 8);
    if (live && t == 0)
        scores[((size_t)bh * S_ + q) * S_ + k] =
            part * 0.125f * gate[((size_t)b * S_ + q) * S_ + k] + amask[b * S_ + k];
}

// ---------------------------------------------------------------------------
// 3b) Dense rows q >= P-1: tiled 64x64 GEMM with NEG fast paths (unchanged).
// ---------------------------------------------------------------------------
__global__ __launch_bounds__(256) void scores_dense_kernel(
        const float* __restrict__ gate, const float* __restrict__ amask,
        const int* __restrict__ feat_len, const int* __restrict__ ppos,
        float* __restrict__ scores) {
    int kt = blockIdx.x, qt = blockIdx.y, bh = blockIdx.z;
    int b = bh / NH_;
    int P = ppos ? ppos[0] : 512;
    int q0 = qt * 64, k0 = kt * 64;
    if (q0 + 63 < P - 1) return;
    int fl = feat_len[b];
    int lo0 = max(0, fl - 1), hi0 = P;
    bool hasPm1 = (P-1 >= q0) && (P-1 < q0 + 64);
    bool spanOv = (lo0 < hi0) && (k0 < hi0) && (k0 + 64 > lo0) && (q0 + 63 >= P);
    int tid = threadIdx.x;

    if (!hasPm1 && !spanOv) {
        float4 neg4 = make_float4(NEGV, NEGV, NEGV, NEGV);
        int kc = k0 + (tid & 15) * 4;
        #pragma unroll
        for (int it = 0; it < 4; it++) {
            int q = q0 + (tid >> 4) + it * 16;
            if (q >= P-1)
                *reinterpret_cast<float4*>(
                    scores + ((size_t)bh * S_ + q) * S_ + kc) = neg4;
        }
        return;
    }

    if (hasPm1 && !spanOv) {
        int q = P - 1;
        int kk = tid >> 2;
        int dc = (tid & 3) * 16;
        const float4* qp = reinterpret_cast<const float4*>(
            g_q + ((size_t)bh * S_ + q) * DH_ + dc);
        const float4* kp = reinterpret_cast<const float4*>(
            g_k + ((size_t)bh * S_ + k0 + kk) * DH_ + dc);
        float part = 0.f;
        #pragma unroll
        for (int i = 0; i < 4; i++) {
            float4 a = qp[i], v = kp[i];
            part += a.x*v.x + a.y*v.y + a.z*v.z + a.w*v.w;
        }
        part += __shfl_xor_sync(0xffffffffu, part, 1);
        part += __shfl_xor_sync(0xffffffffu, part, 2);
        if ((tid & 3) == 0) {
            int k = k0 + kk;
            scores[((size_t)bh * S_ + q) * S_ + k] =
                part * 0.125f * gate[((size_t)b * S_ + q) * S_ + k] + amask[b * S_ + k];
        }
        float4 neg4 = make_float4(NEGV, NEGV, NEGV, NEGV);
        int kc = k0 + (tid & 15) * 4;
        #pragma unroll
        for (int it = 0; it < 4; it++) {
            int q2 = q0 + (tid >> 4) + it * 16;
            if (q2 >= P)
                *reinterpret_cast<float4*>(
                    scores + ((size_t)bh * S_ + q2) * S_ + kc) = neg4;
        }
        return;
    }

    __shared__ float Qs[DH_][68];
    __shared__ float Ks[DH_][68];
    #pragma unroll
    for (int it = 0; it < 4; it++) {
        int idx = tid + it * 256;
        int r = idx >> 4, c4 = (idx & 15) * 4;
        float4 qv = *reinterpret_cast<const float4*>(
            g_q + ((size_t)bh * S_ + q0 + r) * DH_ + c4);
        float4 kv = *reinterpret_cast<const float4*>(
            g_k + ((size_t)bh * S_ + k0 + r) * DH_ + c4);
        Qs[c4+0][r] = qv.x; Qs[c4+1][r] = qv.y; Qs[c4+2][r] = qv.z; Qs[c4+3][r] = qv.w;
        Ks[c4+0][r] = kv.x; Ks[c4+1][r] = kv.y; Ks[c4+2][r] = kv.z; Ks[c4+3][r] = kv.w;
    }
    __syncthreads();

    int tq = tid >> 4, tk = tid & 15;
    float acc[4][4];
    #pragma unroll
    for (int i = 0; i < 4; i++)
        #pragma unroll
        for (int j = 0; j < 4; j++) acc[i][j] = 0.f;

    #pragma unroll 4
    for (int d = 0; d < DH_; d++) {
        float4 qv = *reinterpret_cast<float4*>(&Qs[d][tq*4]);
        float4 kv = *reinterpret_cast<float4*>(&Ks[d][tk*4]);
        float qa[4] = {qv.x, qv.y, qv.z, qv.w};
        float ka[4] = {kv.x, kv.y, kv.z, kv.w};
        #pragma unroll
        for (int i = 0; i < 4; i++)
            #pragma unroll
            for (int j = 0; j < 4; j++)
                acc[i][j] += qa[i] * ka[j];
    }

    #pragma unroll
    for (int i = 0; i < 4; i++) {
        int q = q0 + tq*4 + i;
        if (q < P-1) continue;
        bool full = (q == P-1);
        float res[4];
        #pragma unroll
        for (int j = 0; j < 4; j++) {
            int k = k0 + tk*4 + j;
            bool masked = !full && ((k >= P) || (k < fl-1));
            res[j] = masked ? NEGV
                   : acc[i][j] * 0.125f * gate[((size_t)b * S_ + q) * S_ + k]
                     + amask[b * S_ + k];
        }
        *reinterpret_cast<float4*>(
            scores + ((size_t)bh * S_ + q) * S_ + k0 + tk*4)
            = make_float4(res[0], res[1], res[2], res[3]);
    }
}

// ---------------------------------------------------------------------------
// 4a) Rows q < P-1: only k in {q-1, q} survive. out = softmax2 . v
// ---------------------------------------------------------------------------
__global__ void softmax_sparse_kernel(const float* __restrict__ scores,
                                      const int* __restrict__ ppos,
                                      float* __restrict__ out) {
    int tid = threadIdx.x;
    int R = blockIdx.x * 4 + (tid >> 6);
    int d = tid & 63;
    int bh = R >> 10;
    int q  = R & 1023;
    int P  = ppos ? ppos[0] : 512;
    if (q >= P-1) return;
    int b = bh / NH_, h = bh % NH_;
    const float* srow = scores + (size_t)R * S_;

    float val;
    if (q == 0) {
        val = g_v[((size_t)bh * S_) * DH_ + d];
    } else {
        float s0 = srow[q-1], s1 = srow[q];
        float m = fmaxf(s0, s1);
        float p0 = expf(s0 - m), p1 = expf(s1 - m);
        float inv = 1.f / (p0 + p1);
        val = (p0 * g_v[((size_t)bh*S_ + q-1)*DH_ + d]
             + p1 * g_v[((size_t)bh*S_ + q  )*DH_ + d]) * inv;
    }
    out[((size_t)(b*S_ + q)) * H_ + h*DH_ + d] = val;
}

// ---------------------------------------------------------------------------
// 4b-1) Uniform batches (fl-1 >= P): all q >= P rows are fully masked ->
//       probs = 1/S -> out = column mean of V, same for every such row.
// ---------------------------------------------------------------------------
__global__ __launch_bounds__(256) void vmean_bcast_kernel(
        const int* __restrict__ feat_len, const int* __restrict__ ppos,
        float* __restrict__ out) {
    int bh = blockIdx.x;
    int b = bh / NH_, h = bh % NH_;
    int P = ppos ? ppos[0] : 512;
    int fl = feat_len[b];
    if (max(0, fl - 1) < P) return;            // not uniform: pv_tiled owns rows
    int tid = threadIdx.x;
    int d = tid & 63, kg = tid >> 6;
    float s = 0.f;
    for (int k = kg*256; k < kg*256 + 256; k++)
        s += g_v[((size_t)bh * S_ + k) * DH_ + d];
    __shared__ float red[256];
    red[tid] = s; __syncthreads();
    if (kg == 0)
        red[d] = (red[d] + red[64+d] + red[128+d] + red[192+d]) * (1.0f / S_);
    __syncthreads();
    float m = red[d];
    for (int q = P + kg; q < S_; q += 4)
        out[((size_t)(b*S_ + q)) * H_ + h*DH_ + d] = m;
}

// ---------------------------------------------------------------------------
// 4b-2) Rows q >= P-1: tiled softmax+PV. Uniform batches: only row P-1 here.
// ---------------------------------------------------------------------------
#define QT 32
#define KTILE 64
__global__ __launch_bounds__(256) void pv_tiled_kernel(
        const float* __restrict__ scores, const int* __restrict__ feat_len,
        const int* __restrict__ ppos, float* __restrict__ out) {
    int bh = blockIdx.y;
    int b = bh / NH_, h = bh % NH_;
    int P = ppos ? ppos[0] : 512;
    int q0 = blockIdx.x * QT;
    if (q0 + QT <= P-1) return;
    int fl = feat_len[b];
    int lo0 = max(0, fl - 1), hi0 = P;
    bool uniformB = (lo0 >= hi0);              // q>=P rows handled by vmean_bcast
    bool hasPm1 = (P-1 >= q0) && (P-1 < q0 + QT);
    bool hasGE  = (q0 + QT > P) && !uniformB;
    if (!hasPm1 && !hasGE) return;
    int ulo = hasPm1 ? 0 : lo0;
    int uhi = hasPm1 ? S_ : hi0;               // hasPm1 union is [0,S) anyway

    __shared__ float Vs[KTILE][DH_ + 4];
    __shared__ float Ps[QT][KTILE];
    __shared__ float Ms[QT], Is[QT];

    int tid = threadIdx.x;
    int w = tid >> 5, lane = tid & 31;

    for (int rr = 0; rr < 4; rr++) {
        int r = w*4 + rr;
        int q = q0 + r;
        bool act = (q == P-1) || (q >= P && !uniformB);
        if (!act) continue;
        int rlo = (q == P-1) ? 0  : lo0;
        int rhi = (q == P-1) ? S_ : hi0;
        const float* srow = scores + ((size_t)bh * S_ + q) * S_;
        float m = -INFINITY;
        for (int k = rlo + lane; k < rhi; k += 32) m = fmaxf(m, srow[k]);
        #pragma unroll
        for (int off = 16; off > 0; off >>= 1)
            m = fmaxf(m, __shfl_xor_sync(0xffffffffu, m, off));
        float s = 0.f;
        for (int k = rlo + lane; k < rhi; k += 32) s += expf(srow[k] - m);
        #pragma unroll
        for (int off = 16; off > 0; off >>= 1)
            s += __shfl_xor_sync(0xffffffffu, s, off);
        if (lane == 0) { Ms[r] = m; Is[r] = 1.f / s; }
    }
    __syncthreads();

    int d = tid & 63;
    int g = tid >> 6;
    float acc[8];
    #pragma unroll
    for (int j = 0; j < 8; j++) acc[j] = 0.f;

    int pr  = tid >> 3;
    int pq  = q0 + pr;
    int pk0 = (tid & 7) * 8;
    bool pact = (pq == P-1) || (pq >= P && !uniformB);
    int prlo = (pq == P-1) ? 0  : lo0;
    int prhi = (pq == P-1) ? S_ : hi0;
    float pM = 0.f, pI = 0.f;
    if (pact) { pM = Ms[pr]; pI = Is[pr]; }
    const float* psrow = scores + ((size_t)bh * S_ + pq) * S_;

    for (int kt = ulo; kt < uhi; kt += KTILE) {
        __syncthreads();
        #pragma unroll
        for (int it = 0; it < 4; it++) {
            int idx = tid + it * 256;
            int r = idx >> 4, c4 = (idx & 15) * 4;
            float4 v4 = make_float4(0.f, 0.f, 0.f, 0.f);
            if (kt + r < uhi)
                v4 = *reinterpret_cast<const float4*>(
                    g_v + ((size_t)bh * S_ + kt + r) * DH_ + c4);
            *reinterpret_cast<float4*>(&Vs[r][c4]) = v4;
        }
        #pragma unroll
        for (int j = 0; j < 8; j++) {
            int k = kt + pk0 + j;
            float p = 0.f;
            if (pact && k >= prlo && k < prhi) p = expf(psrow[k] - pM) * pI;
            Ps[pr][pk0 + j] = p;
        }
        __syncthreads();
        #pragma unroll 8
        for (int kk = 0; kk < KTILE; kk++) {
            float vv = Vs[kk][d];
            #pragma unroll
            for (int j = 0; j < 8; j++)
                acc[j] += Ps[g*8 + j][kk] * vv;
        }
    }

    #pragma unroll
    for (int j = 0; j < 8; j++) {
        int q = q0 + g*8 + j;
        bool act = (q == P-1) || (q >= P && !uniformB);
        if (act)
            out[((size_t)(b*S_ + q)) * H_ + h*DH_ + d] = acc[j];
    }
}

// ---------------------------------------------------------------------------
extern "C" void kernel_launch(void* const* d_in, const int* in_sizes, int n_in,
                              void* d_out, int out_size) {
    const float* hidden  = (const float*)d_in[0];
    const float* context = (const float*)d_in[1];
    const float* amask   = (const float*)d_in[2];
    const float* gate    = (const float*)d_in[3];
    const float* vis     = (const float*)d_in[4];
    const float* Wq      = (const float*)d_in[5];
    const float* bq      = (const float*)d_in[6];
    const float* Wk      = (const float*)d_in[7];
    const float* bk      = (const float*)d_in[8];
    const float* Wv      = (const float*)d_in[9];
    const float* bv      = (const float*)d_in[10];
    const int*   feat_len= (const int*)  d_in[11];
    const int*   ppos    = (n_in > 12) ? (const int*)d_in[12] : nullptr;

    float* out    = (float*)d_out;                       // (B,S,H)
    float* scores = out + (size_t)B_ * S_ * H_;          // (B,NH,S,S)

    split_a_kernel<<<(B_*S_*H_/8 + 255)/256, 256>>>(
        (const float4*)hidden, (const float4*)context,
        (const float4*)vis, feat_len);
    split_w_kernel<<<(3*H_*H_/8 + 255)/256, 256>>>(
        (const float4*)Wq, (const float4*)Wk, (const float4*)Wv);

    dim3 gg((B_*S_)/128, H_/128, 3);
    qkv_mma_kernel<<<gg, 256>>>(bq, bk, bv);

    band_fill_kernel<<<dim3(S_/4, B_*NH_), 256>>>(ppos, scores);
    band_dots_kernel<<<(B_*NH_*S_)/8, 256>>>(gate, amask, ppos, scores);
    scores_dense_kernel<<<dim3(S_/64, S_/64, B_*NH_), 256>>>(
        gate, amask, feat_len, ppos, scores);

    softmax_sparse_kernel<<<(B_*NH_*S_)/4, 256>>>(scores, ppos, out);
    vmean_bcast_kernel<<<B_*NH_, 256>>>(feat_len, ppos, out);
    pv_tiled_kernel<<<dim3(S_/QT, B_*NH_), 256>>>(scores, feat_len, ppos, out);
}